// round 1
// baseline (speedup 1.0000x reference)
#include <cuda_runtime.h>
#include <math.h>

// ---------------------------------------------------------------------------
// Problem constants
// ---------------------------------------------------------------------------
#define R_RAYS   8192
#define S_SAMP   64
#define NSAMP    (R_RAYS * S_SAMP)      // 524288
#define C_FEAT   32

// Combos (j,k) indexing p4 = (x,y,z,t)
__device__ __constant__ int d_J[6] = {0,0,0,1,1,2};
__device__ __constant__ int d_K[6] = {1,2,3,2,3,3};

// Coarse plane widths (h = 64 for all)
__device__ __constant__ int d_cw[6]    = {64,64,50,64,50,50};
__device__ __constant__ int d_cbase[6] = {0,4096,8192,11392,15488,18688};   // coarse texel base
#define N_COARSE 21888

// Fine plane widths (H = 128 for all), W = 2w
__device__ __constant__ int d_fw[6]    = {128,128,100,128,100,100};
__device__ __constant__ int d_fbase[6] = {0,16384,32768,45568,61952,74752}; // fine texel base
#define N_FINE 87552

// ---------------------------------------------------------------------------
// Scratch (device globals; no runtime allocation allowed)
// ---------------------------------------------------------------------------
__device__ float g_hi[N_FINE * C_FEAT];       // 11.2 MB  [texel][c]
__device__ float g_lo[N_FINE * C_FEAT];       // 11.2 MB
__device__ float g_feats[64 * NSAMP];         // 134 MB, feature-major [f][n]
__device__ float g_enc[R_RAYS * 16];          // SH encodings per ray

// ---------------------------------------------------------------------------
// Kernel 1: expand (yl, yh) -> hi / lo fine planes, channel-fastest layout
// One warp per coarse cell; lane = channel.
// ---------------------------------------------------------------------------
__global__ void expand_kernel(
    const float* __restrict__ yl0, const float* __restrict__ yh0,
    const float* __restrict__ yl1, const float* __restrict__ yh1,
    const float* __restrict__ yl2, const float* __restrict__ yh2,
    const float* __restrict__ yl3, const float* __restrict__ yh3,
    const float* __restrict__ yl4, const float* __restrict__ yh4,
    const float* __restrict__ yl5, const float* __restrict__ yh5)
{
    const float* yls[6] = {yl0, yl1, yl2, yl3, yl4, yl5};
    const float* yhs[6] = {yh0, yh1, yh2, yh3, yh4, yh5};

    int warpIdx = (blockIdx.x * blockDim.x + threadIdx.x) >> 5;
    int lane    = threadIdx.x & 31;
    if (warpIdx >= N_COARSE) return;

    int p = 0;
    #pragma unroll
    for (int q = 1; q < 6; q++) if (warpIdx >= d_cbase[q]) p = q;

    int local = warpIdx - d_cbase[p];
    int w  = d_cw[p];
    int cy = local / w;
    int cx = local - cy * w;
    int hw = 64 * w;

    const float* yl = yls[p];
    const float* yh = yhs[p];

    float a  = yl[lane * hw + cy * w + cx];
    const float* yhc = yh + (size_t)lane * 3 * hw + cy * w + cx;
    float lh = yhc[0];
    float hl = yhc[hw];
    float hh = yhc[2 * hw];

    int W    = 2 * w;
    int base = d_fbase[p] + (2 * cy) * W + 2 * cx;
    int i00 = base * 32 + lane;
    int i01 = i00 + 32;
    int i10 = (base + W) * 32 + lane;
    int i11 = i10 + 32;

    g_hi[i00] = 0.5f * (a + lh + hl + hh);
    g_hi[i01] = 0.5f * (a + lh - hl - hh);
    g_hi[i10] = 0.5f * (a - lh + hl - hh);
    g_hi[i11] = 0.5f * (a - lh - hl + hh);

    float lv = 0.5f * a;
    g_lo[i00] = lv; g_lo[i01] = lv; g_lo[i10] = lv; g_lo[i11] = lv;
}

// ---------------------------------------------------------------------------
// Kernel 2: SH degree-4 encoding per ray
// ---------------------------------------------------------------------------
__global__ void sh_kernel(const float* __restrict__ dirs)
{
    int r = blockIdx.x * blockDim.x + threadIdx.x;
    if (r >= R_RAYS) return;
    float dx = dirs[3*r], dy = dirs[3*r+1], dz = dirs[3*r+2];
    float nrm = sqrtf(dx*dx + dy*dy + dz*dz);
    float x = dx / nrm, y = dy / nrm, z = dz / nrm;
    float xx = x*x, yy = y*y, zz = z*z;

    float* e = g_enc + r * 16;
    e[0]  = 0.28209479177387814f;
    e[1]  = -0.4886025119029199f * y;
    e[2]  =  0.4886025119029199f * z;
    e[3]  = -0.4886025119029199f * x;
    e[4]  =  1.0925484305920792f * x * y;
    e[5]  = -1.0925484305920792f * y * z;
    e[6]  =  0.31539156525252005f * (3.0f * zz - 1.0f);
    e[7]  = -1.0925484305920792f * x * z;
    e[8]  =  0.5462742152960396f * (xx - yy);
    e[9]  = -0.5900435899266435f * y * (3.0f * xx - yy);
    e[10] =  2.890611442640554f * x * y * z;
    e[11] = -0.4570457994644658f * y * (5.0f * zz - 1.0f);
    e[12] =  0.3731763325901154f * z * (5.0f * zz - 3.0f);
    e[13] = -0.4570457994644658f * x * (5.0f * zz - 1.0f);
    e[14] =  1.445305721320277f * z * (xx - yy);
    e[15] = -0.5900435899266435f * x * (xx - 3.0f * yy);
}

// ---------------------------------------------------------------------------
// Kernel 3: gather + bilerp + 6-way product -> g_feats (feature-major)
// 4 warps / block; each warp handles 32 samples; lane = channel.
// Dynamic smem per warp: 1152 words addr/weight + 64x33 transpose tile.
// ---------------------------------------------------------------------------
#define GW_AW    1152              // 32 samples * 6 combos * 6 words
#define GW_TILE  (64 * 33)
#define GW_WORDS (GW_AW + GW_TILE) // 3264
#define GATHER_SMEM (4 * GW_WORDS * 4)  // 52224 bytes

__global__ void gather_kernel(const float* __restrict__ pts,
                              const float* __restrict__ tstamps)
{
    extern __shared__ float smem[];
    int warp = threadIdx.x >> 5;
    int lane = threadIdx.x & 31;

    float* aw   = smem + warp * GW_WORDS;
    float* tile = aw + GW_AW;

    int n0 = (blockIdx.x * 4 + warp) * 32;
    int n  = n0 + lane;

    // ---- phase 1: each lane computes addresses/weights for its own sample
    float p4[4];
    p4[0] = pts[3*n + 0];
    p4[1] = pts[3*n + 1];
    p4[2] = pts[3*n + 2];
    p4[3] = tstamps[n >> 6] * 2.0f - 1.0f;

    #pragma unroll
    for (int m = 0; m < 6; m++) {
        float cy_ = p4[d_J[m]];
        float cx_ = p4[d_K[m]];
        int W = d_fw[m];

        float y = (cy_ + 1.0f) * 0.5f * 127.0f;
        float x = (cx_ + 1.0f) * 0.5f * (float)(W - 1);

        float fy = floorf(y);
        int y0 = (int)fminf(fmaxf(fy, 0.0f), 127.0f);
        float wy = fminf(fmaxf(y - (float)y0, 0.0f), 1.0f);
        int y1 = min(y0 + 1, 127);

        float fx = floorf(x);
        int x0 = (int)fminf(fmaxf(fx, 0.0f), (float)(W - 1));
        float wx = fminf(fmaxf(x - (float)x0, 0.0f), 1.0f);
        int x1 = min(x0 + 1, W - 1);

        int b = d_fbase[m];
        int a00 = (b + y0 * W + x0) * 32;
        int a01 = (b + y0 * W + x1) * 32;
        int a10 = (b + y1 * W + x0) * 32;
        int a11 = (b + y1 * W + x1) * 32;

        float* s = aw + lane * 36 + m * 6;
        ((int*)s)[0] = a00;
        ((int*)s)[1] = a01;
        ((int*)s)[2] = a10;
        ((int*)s)[3] = a11;
        s[4] = wy;
        s[5] = wx;
    }
    __syncwarp();

    // ---- phase 2: process the 32 samples; lane = channel
    for (int i = 0; i < 32; i++) {
        float ah = 1.0f, al = 1.0f;
        #pragma unroll
        for (int m = 0; m < 6; m++) {
            const float* s = aw + i * 36 + m * 6;
            int a00 = ((const int*)s)[0];
            int a01 = ((const int*)s)[1];
            int a10 = ((const int*)s)[2];
            int a11 = ((const int*)s)[3];
            float wy = s[4];
            float wx = s[5];
            float w00 = (1.0f - wy) * (1.0f - wx);
            float w01 = (1.0f - wy) * wx;
            float w10 = wy * (1.0f - wx);
            float w11 = wy * wx;

            float vh = w00 * __ldg(g_hi + a00 + lane)
                     + w01 * __ldg(g_hi + a01 + lane)
                     + w10 * __ldg(g_hi + a10 + lane)
                     + w11 * __ldg(g_hi + a11 + lane);
            float vl = w00 * __ldg(g_lo + a00 + lane)
                     + w01 * __ldg(g_lo + a01 + lane)
                     + w10 * __ldg(g_lo + a10 + lane)
                     + w11 * __ldg(g_lo + a11 + lane);
            ah *= vh;
            al *= vl;
        }
        tile[lane * 33 + i]        = ah;   // hi features: rows 0..31
        tile[(32 + lane) * 33 + i] = al;   // lo features: rows 32..63
    }
    __syncwarp();

    // ---- phase 3: coalesced feature-major writes
    #pragma unroll 8
    for (int r = 0; r < 64; r++) {
        g_feats[r * NSAMP + n0 + lane] = tile[r * 33 + lane];
    }
}

// ---------------------------------------------------------------------------
// Kernel 4: fused MLP. Thread per sample; all weights in shared memory.
// ---------------------------------------------------------------------------
#define SW1_OFF  0        // Wsig1 [64][64]
#define SW2_OFF  4096     // Wsig2 [64][16]
#define SC1_OFF  5120     // Wc1   [31][64]
#define SC2_OFF  7104     // Wc2   [64][64]
#define SC3_OFF  11200    // Wc3   [64][3]
#define SW_TOTAL 11392

__global__ void __launch_bounds__(128) mlp_kernel(
    const float* __restrict__ Ws1, const float* __restrict__ Ws2,
    const float* __restrict__ Wc1, const float* __restrict__ Wc2,
    const float* __restrict__ Wc3, float* __restrict__ out)
{
    __shared__ __align__(16) float sW[SW_TOTAL];
    for (int i = threadIdx.x; i < 4096; i += 128) sW[SW1_OFF + i] = Ws1[i];
    for (int i = threadIdx.x; i < 1024; i += 128) sW[SW2_OFF + i] = Ws2[i];
    for (int i = threadIdx.x; i < 1984; i += 128) sW[SC1_OFF + i] = Wc1[i];
    for (int i = threadIdx.x; i < 4096; i += 128) sW[SC2_OFF + i] = Wc2[i];
    for (int i = threadIdx.x; i <  192; i += 128) sW[SC3_OFF + i] = Wc3[i];
    __syncthreads();

    int n = blockIdx.x * 128 + threadIdx.x;

    // ---- layer 1: feats[64] @ Wsig1[64][64] -> A
    float A[64];
    #pragma unroll
    for (int j = 0; j < 64; j++) A[j] = 0.0f;

    #pragma unroll 4
    for (int k = 0; k < 64; k++) {
        float f = g_feats[k * NSAMP + n];
        const float4* w = (const float4*)(sW + SW1_OFF + k * 64);
        #pragma unroll
        for (int jj = 0; jj < 16; jj++) {
            float4 ww = w[jj];
            A[4*jj+0] += f * ww.x;
            A[4*jj+1] += f * ww.y;
            A[4*jj+2] += f * ww.z;
            A[4*jj+3] += f * ww.w;
        }
    }

    // ---- layer 2: relu(A) @ Wsig2[64][16] -> o
    float o[16];
    #pragma unroll
    for (int j = 0; j < 16; j++) o[j] = 0.0f;
    #pragma unroll 4
    for (int k = 0; k < 64; k++) {
        float hk = fmaxf(A[k], 0.0f);
        const float4* w = (const float4*)(sW + SW2_OFF + k * 16);
        #pragma unroll
        for (int jj = 0; jj < 4; jj++) {
            float4 ww = w[jj];
            o[4*jj+0] += hk * ww.x;
            o[4*jj+1] += hk * ww.y;
            o[4*jj+2] += hk * ww.z;
            o[4*jj+3] += hk * ww.w;
        }
    }

    float density = expf(fminf(fmaxf(o[15], -15.0f), 15.0f));
    int ray = n >> 6;

    // ---- layer 3: ci[31] @ Wc1[31][64] -> A (reused)
    #pragma unroll
    for (int j = 0; j < 64; j++) A[j] = 0.0f;
    #pragma unroll 4
    for (int k = 0; k < 31; k++) {
        float cik = (k < 16) ? g_enc[ray * 16 + k] : o[k - 16];
        const float4* w = (const float4*)(sW + SC1_OFF + k * 64);
        #pragma unroll
        for (int jj = 0; jj < 16; jj++) {
            float4 ww = w[jj];
            A[4*jj+0] += cik * ww.x;
            A[4*jj+1] += cik * ww.y;
            A[4*jj+2] += cik * ww.z;
            A[4*jj+3] += cik * ww.w;
        }
    }

    // ---- layer 4: relu(A) @ Wc2[64][64] -> B
    float B[64];
    #pragma unroll
    for (int j = 0; j < 64; j++) B[j] = 0.0f;
    #pragma unroll 2
    for (int k = 0; k < 64; k++) {
        float hk = fmaxf(A[k], 0.0f);
        const float4* w = (const float4*)(sW + SC2_OFF + k * 64);
        #pragma unroll
        for (int jj = 0; jj < 16; jj++) {
            float4 ww = w[jj];
            B[4*jj+0] += hk * ww.x;
            B[4*jj+1] += hk * ww.y;
            B[4*jj+2] += hk * ww.z;
            B[4*jj+3] += hk * ww.w;
        }
    }

    // ---- layer 5: relu(B) @ Wc3[64][3] -> rgb, sigmoid
    float r0 = 0.0f, r1 = 0.0f, r2 = 0.0f;
    #pragma unroll 4
    for (int k = 0; k < 64; k++) {
        float hk = fmaxf(B[k], 0.0f);
        const float* w = sW + SC3_OFF + k * 3;
        r0 += hk * w[0];
        r1 += hk * w[1];
        r2 += hk * w[2];
    }

    out[4*n + 0] = 1.0f / (1.0f + expf(-r0));
    out[4*n + 1] = 1.0f / (1.0f + expf(-r1));
    out[4*n + 2] = 1.0f / (1.0f + expf(-r2));
    out[4*n + 3] = density;
}

// ---------------------------------------------------------------------------
// Launch
// ---------------------------------------------------------------------------
extern "C" void kernel_launch(void* const* d_in, const int* in_sizes, int n_in,
                              void* d_out, int out_size)
{
    const float* pts   = (const float*)d_in[0];
    const float* dirs  = (const float*)d_in[1];
    const float* ts    = (const float*)d_in[2];
    const float* yl[6], *yh[6];
    for (int i = 0; i < 6; i++) {
        yl[i] = (const float*)d_in[3 + 2*i];
        yh[i] = (const float*)d_in[4 + 2*i];
    }
    const float* Ws1 = (const float*)d_in[15];
    const float* Ws2 = (const float*)d_in[16];
    const float* Wc1 = (const float*)d_in[17];
    const float* Wc2 = (const float*)d_in[18];
    const float* Wc3 = (const float*)d_in[19];
    float* out = (float*)d_out;

    static bool attr_done = false;
    if (!attr_done) {
        cudaFuncSetAttribute(gather_kernel,
                             cudaFuncAttributeMaxDynamicSharedMemorySize,
                             GATHER_SMEM);
        attr_done = true;
    }

    // 1) expand planes: 21888 coarse cells, 8 warps/block
    expand_kernel<<<(N_COARSE + 7) / 8, 256>>>(
        yl[0], yh[0], yl[1], yh[1], yl[2], yh[2],
        yl[3], yh[3], yl[4], yh[4], yl[5], yh[5]);

    // 2) SH encodings
    sh_kernel<<<R_RAYS / 256, 256>>>(dirs);

    // 3) gather + product
    gather_kernel<<<NSAMP / 128, 128, GATHER_SMEM>>>(pts, ts);

    // 4) MLP
    mlp_kernel<<<NSAMP / 128, 128>>>(Ws1, Ws2, Wc1, Wc2, Wc3, out);
}

// round 3
// speedup vs baseline: 1.5578x; 1.5578x over previous
#include <cuda_runtime.h>
#include <math.h>

// ---------------------------------------------------------------------------
// Problem constants
// ---------------------------------------------------------------------------
#define R_RAYS   8192
#define S_SAMP   64
#define NSAMP    (R_RAYS * S_SAMP)      // 524288
#define C_FEAT   32

// Combos (j,k) indexing p4 = (x,y,z,t)
__device__ __constant__ int d_J[6] = {0,0,0,1,1,2};
__device__ __constant__ int d_K[6] = {1,2,3,2,3,3};

// Coarse plane widths (h = 64 for all)
__device__ __constant__ int d_cw[6]    = {64,64,50,64,50,50};
__device__ __constant__ int d_cbase[6] = {0,4096,8192,11392,15488,18688};
#define N_COARSE 21888

// Fine plane widths (H = 128 for all), W = 2w
__device__ __constant__ int d_fw[6]    = {128,128,100,128,100,100};
__device__ __constant__ int d_fbase[6] = {0,16384,32768,45568,61952,74752};
#define N_FINE 87552

// ---------------------------------------------------------------------------
// Scratch (device globals; no runtime allocation allowed)
// ---------------------------------------------------------------------------
__device__ float g_hi[N_FINE * C_FEAT];       // 11.2 MB  [texel][c]
__device__ float g_lo[N_FINE * C_FEAT];       // 11.2 MB
__device__ float g_feats[64 * NSAMP];         // 134 MB, feature-major [f][n]
__device__ float g_enc[R_RAYS * 16];          // SH encodings per ray

// ---------------------------------------------------------------------------
// f32x2 packed-FMA helpers (Blackwell FFMA2 — only reachable via PTX)
// ---------------------------------------------------------------------------
__device__ __forceinline__ unsigned long long dup2(float f) {
    unsigned long long r;
    asm("mov.b64 %0, {%1, %1};" : "=l"(r) : "r"(__float_as_uint(f)));
    return r;
}
__device__ __forceinline__ void ffma2(unsigned long long& d,
                                      unsigned long long a,
                                      unsigned long long b) {
    asm("fma.rn.f32x2 %0, %1, %2, %0;" : "+l"(d) : "l"(a), "l"(b));
}
__device__ __forceinline__ float2 unpk(unsigned long long v) {
    unsigned lo, hi;
    asm("mov.b64 {%0, %1}, %2;" : "=r"(lo), "=r"(hi) : "l"(v));
    float2 r;
    r.x = __uint_as_float(lo);
    r.y = __uint_as_float(hi);
    return r;
}

// ---------------------------------------------------------------------------
// Kernel 1: expand (yl, yh) -> hi / lo fine planes, channel-fastest layout
// ---------------------------------------------------------------------------
__global__ void expand_kernel(
    const float* __restrict__ yl0, const float* __restrict__ yh0,
    const float* __restrict__ yl1, const float* __restrict__ yh1,
    const float* __restrict__ yl2, const float* __restrict__ yh2,
    const float* __restrict__ yl3, const float* __restrict__ yh3,
    const float* __restrict__ yl4, const float* __restrict__ yh4,
    const float* __restrict__ yl5, const float* __restrict__ yh5)
{
    const float* yls[6] = {yl0, yl1, yl2, yl3, yl4, yl5};
    const float* yhs[6] = {yh0, yh1, yh2, yh3, yh4, yh5};

    int warpIdx = (blockIdx.x * blockDim.x + threadIdx.x) >> 5;
    int lane    = threadIdx.x & 31;
    if (warpIdx >= N_COARSE) return;

    int p = 0;
    #pragma unroll
    for (int q = 1; q < 6; q++) if (warpIdx >= d_cbase[q]) p = q;

    int local = warpIdx - d_cbase[p];
    int w  = d_cw[p];
    int cy = local / w;
    int cx = local - cy * w;
    int hw = 64 * w;

    const float* yl = yls[p];
    const float* yh = yhs[p];

    float a  = yl[lane * hw + cy * w + cx];
    const float* yhc = yh + (size_t)lane * 3 * hw + cy * w + cx;
    float lh = yhc[0];
    float hl = yhc[hw];
    float hh = yhc[2 * hw];

    int W    = 2 * w;
    int base = d_fbase[p] + (2 * cy) * W + 2 * cx;
    int i00 = base * 32 + lane;
    int i01 = i00 + 32;
    int i10 = (base + W) * 32 + lane;
    int i11 = i10 + 32;

    g_hi[i00] = 0.5f * (a + lh + hl + hh);
    g_hi[i01] = 0.5f * (a + lh - hl - hh);
    g_hi[i10] = 0.5f * (a - lh + hl - hh);
    g_hi[i11] = 0.5f * (a - lh - hl + hh);

    float lv = 0.5f * a;
    g_lo[i00] = lv; g_lo[i01] = lv; g_lo[i10] = lv; g_lo[i11] = lv;
}

// ---------------------------------------------------------------------------
// Kernel 2: SH degree-4 encoding per ray
// ---------------------------------------------------------------------------
__global__ void sh_kernel(const float* __restrict__ dirs)
{
    int r = blockIdx.x * blockDim.x + threadIdx.x;
    if (r >= R_RAYS) return;
    float dx = dirs[3*r], dy = dirs[3*r+1], dz = dirs[3*r+2];
    float nrm = sqrtf(dx*dx + dy*dy + dz*dz);
    float x = dx / nrm, y = dy / nrm, z = dz / nrm;
    float xx = x*x, yy = y*y, zz = z*z;

    float* e = g_enc + r * 16;
    e[0]  = 0.28209479177387814f;
    e[1]  = -0.4886025119029199f * y;
    e[2]  =  0.4886025119029199f * z;
    e[3]  = -0.4886025119029199f * x;
    e[4]  =  1.0925484305920792f * x * y;
    e[5]  = -1.0925484305920792f * y * z;
    e[6]  =  0.31539156525252005f * (3.0f * zz - 1.0f);
    e[7]  = -1.0925484305920792f * x * z;
    e[8]  =  0.5462742152960396f * (xx - yy);
    e[9]  = -0.5900435899266435f * y * (3.0f * xx - yy);
    e[10] =  2.890611442640554f * x * y * z;
    e[11] = -0.4570457994644658f * y * (5.0f * zz - 1.0f);
    e[12] =  0.3731763325901154f * z * (5.0f * zz - 3.0f);
    e[13] = -0.4570457994644658f * x * (5.0f * zz - 1.0f);
    e[14] =  1.445305721320277f * z * (xx - yy);
    e[15] = -0.5900435899266435f * x * (xx - 3.0f * yy);
}

// ---------------------------------------------------------------------------
// Kernel 3: gather + bilerp + 6-way product -> g_feats (feature-major)
// ---------------------------------------------------------------------------
#define GW_AW    1152
#define GW_TILE  (64 * 33)
#define GW_WORDS (GW_AW + GW_TILE)
#define GATHER_SMEM (4 * GW_WORDS * 4)

__global__ void gather_kernel(const float* __restrict__ pts,
                              const float* __restrict__ tstamps)
{
    extern __shared__ float smem[];
    int warp = threadIdx.x >> 5;
    int lane = threadIdx.x & 31;

    float* aw   = smem + warp * GW_WORDS;
    float* tile = aw + GW_AW;

    int n0 = (blockIdx.x * 4 + warp) * 32;
    int n  = n0 + lane;

    float p4[4];
    p4[0] = pts[3*n + 0];
    p4[1] = pts[3*n + 1];
    p4[2] = pts[3*n + 2];
    p4[3] = tstamps[n >> 6] * 2.0f - 1.0f;

    #pragma unroll
    for (int m = 0; m < 6; m++) {
        float cy_ = p4[d_J[m]];
        float cx_ = p4[d_K[m]];
        int W = d_fw[m];

        float y = (cy_ + 1.0f) * 0.5f * 127.0f;
        float x = (cx_ + 1.0f) * 0.5f * (float)(W - 1);

        float fy = floorf(y);
        int y0 = (int)fminf(fmaxf(fy, 0.0f), 127.0f);
        float wy = fminf(fmaxf(y - (float)y0, 0.0f), 1.0f);
        int y1 = min(y0 + 1, 127);

        float fx = floorf(x);
        int x0 = (int)fminf(fmaxf(fx, 0.0f), (float)(W - 1));
        float wx = fminf(fmaxf(x - (float)x0, 0.0f), 1.0f);
        int x1 = min(x0 + 1, W - 1);

        int b = d_fbase[m];
        int a00 = (b + y0 * W + x0) * 32;
        int a01 = (b + y0 * W + x1) * 32;
        int a10 = (b + y1 * W + x0) * 32;
        int a11 = (b + y1 * W + x1) * 32;

        float* s = aw + lane * 36 + m * 6;
        ((int*)s)[0] = a00;
        ((int*)s)[1] = a01;
        ((int*)s)[2] = a10;
        ((int*)s)[3] = a11;
        s[4] = wy;
        s[5] = wx;
    }
    __syncwarp();

    for (int i = 0; i < 32; i++) {
        float ah = 1.0f, al = 1.0f;
        #pragma unroll
        for (int m = 0; m < 6; m++) {
            const float* s = aw + i * 36 + m * 6;
            int a00 = ((const int*)s)[0];
            int a01 = ((const int*)s)[1];
            int a10 = ((const int*)s)[2];
            int a11 = ((const int*)s)[3];
            float wy = s[4];
            float wx = s[5];
            float w00 = (1.0f - wy) * (1.0f - wx);
            float w01 = (1.0f - wy) * wx;
            float w10 = wy * (1.0f - wx);
            float w11 = wy * wx;

            float vh = w00 * __ldg(g_hi + a00 + lane)
                     + w01 * __ldg(g_hi + a01 + lane)
                     + w10 * __ldg(g_hi + a10 + lane)
                     + w11 * __ldg(g_hi + a11 + lane);
            float vl = w00 * __ldg(g_lo + a00 + lane)
                     + w01 * __ldg(g_lo + a01 + lane)
                     + w10 * __ldg(g_lo + a10 + lane)
                     + w11 * __ldg(g_lo + a11 + lane);
            ah *= vh;
            al *= vl;
        }
        tile[lane * 33 + i]        = ah;
        tile[(32 + lane) * 33 + i] = al;
    }
    __syncwarp();

    #pragma unroll 8
    for (int r = 0; r < 64; r++) {
        g_feats[r * NSAMP + n0 + lane] = tile[r * 33 + lane];
    }
}

// ---------------------------------------------------------------------------
// Kernel 4: fused MLP — 2 samples per thread, f32x2 packed FMA.
// Weight smem layout (floats):
//   SW1 [64][64] @0, SW2 [64][16] @4096, SC1 [31][64] @5120,
//   SC2 [64][64] @7104, SC3 [64][3] @11200  — total 11392
// Scratch: hbuf[2 samples][64 neurons][128 threads] @11392 (16384 floats)
// ---------------------------------------------------------------------------
#define SW1_OFF  0
#define SW2_OFF  4096
#define SC1_OFF  5120
#define SC2_OFF  7104
#define SC3_OFF  11200
#define SW_TOTAL 11392
#define HB_OFF   SW_TOTAL
#define MLP_SMEM ((SW_TOTAL + 2 * 64 * 128) * 4)   // 111104 bytes

__global__ void __launch_bounds__(128) mlp_kernel(
    const float* __restrict__ Ws1, const float* __restrict__ Ws2,
    const float* __restrict__ Wc1, const float* __restrict__ Wc2,
    const float* __restrict__ Wc3, float* __restrict__ out)
{
    extern __shared__ __align__(16) float sm[];
    float* sW  = sm;
    float* hb0 = sm + HB_OFF;              // sample-0 activations [64][128]
    float* hb1 = hb0 + 64 * 128;           // sample-1 activations

    int tid = threadIdx.x;
    for (int i = tid; i < 4096; i += 128) sW[SW1_OFF + i] = Ws1[i];
    for (int i = tid; i < 1024; i += 128) sW[SW2_OFF + i] = Ws2[i];
    for (int i = tid; i < 1984; i += 128) sW[SC1_OFF + i] = Wc1[i];
    for (int i = tid; i < 4096; i += 128) sW[SC2_OFF + i] = Wc2[i];
    for (int i = tid; i <  192; i += 128) sW[SC3_OFF + i] = Wc3[i];
    __syncthreads();

    int n0 = blockIdx.x * 256 + tid;       // sample 0
    int n1 = n0 + 128;                     // sample 1

    // ============== Layer 1: feats[64] @ Wsig1[64][64] ==============
    unsigned long long A0[32], A1[32];     // A*[p] packs neurons (2p, 2p+1)
    #pragma unroll
    for (int p = 0; p < 32; p++) { A0[p] = 0ull; A1[p] = 0ull; }

    #pragma unroll 4
    for (int k = 0; k < 64; k++) {
        unsigned long long f0 = dup2(__ldg(g_feats + k * NSAMP + n0));
        unsigned long long f1 = dup2(__ldg(g_feats + k * NSAMP + n1));
        const ulonglong2* w = (const ulonglong2*)(sW + SW1_OFF + k * 64);
        #pragma unroll
        for (int jj = 0; jj < 16; jj++) {
            ulonglong2 ww = w[jj];
            ffma2(A0[2*jj],   f0, ww.x);
            ffma2(A0[2*jj+1], f0, ww.y);
            ffma2(A1[2*jj],   f1, ww.x);
            ffma2(A1[2*jj+1], f1, ww.y);
        }
    }

    // ============== Layer 2: relu(A) @ Wsig2[64][16] ==============
    unsigned long long O0[8], O1[8];       // O*[q] packs outputs (2q, 2q+1)
    #pragma unroll
    for (int q = 0; q < 8; q++) { O0[q] = 0ull; O1[q] = 0ull; }

    #pragma unroll 4
    for (int p = 0; p < 32; p++) {
        float2 a0 = unpk(A0[p]);
        float2 a1 = unpk(A1[p]);
        unsigned long long e0a = dup2(fmaxf(a0.x, 0.0f));
        unsigned long long e0b = dup2(fmaxf(a0.y, 0.0f));
        unsigned long long e1a = dup2(fmaxf(a1.x, 0.0f));
        unsigned long long e1b = dup2(fmaxf(a1.y, 0.0f));
        const ulonglong2* ra = (const ulonglong2*)(sW + SW2_OFF + (2*p)   * 16);
        const ulonglong2* rb = (const ulonglong2*)(sW + SW2_OFF + (2*p+1) * 16);
        ulonglong2 a0v = ra[0], a1v = ra[1], a2v = ra[2], a3v = ra[3];
        ffma2(O0[0], e0a, a0v.x); ffma2(O0[1], e0a, a0v.y);
        ffma2(O0[2], e0a, a1v.x); ffma2(O0[3], e0a, a1v.y);
        ffma2(O0[4], e0a, a2v.x); ffma2(O0[5], e0a, a2v.y);
        ffma2(O0[6], e0a, a3v.x); ffma2(O0[7], e0a, a3v.y);
        ffma2(O1[0], e1a, a0v.x); ffma2(O1[1], e1a, a0v.y);
        ffma2(O1[2], e1a, a1v.x); ffma2(O1[3], e1a, a1v.y);
        ffma2(O1[4], e1a, a2v.x); ffma2(O1[5], e1a, a2v.y);
        ffma2(O1[6], e1a, a3v.x); ffma2(O1[7], e1a, a3v.y);
        ulonglong2 b0v = rb[0], b1v = rb[1], b2v = rb[2], b3v = rb[3];
        ffma2(O0[0], e0b, b0v.x); ffma2(O0[1], e0b, b0v.y);
        ffma2(O0[2], e0b, b1v.x); ffma2(O0[3], e0b, b1v.y);
        ffma2(O0[4], e0b, b2v.x); ffma2(O0[5], e0b, b2v.y);
        ffma2(O0[6], e0b, b3v.x); ffma2(O0[7], e0b, b3v.y);
        ffma2(O1[0], e1b, b0v.x); ffma2(O1[1], e1b, b0v.y);
        ffma2(O1[2], e1b, b1v.x); ffma2(O1[3], e1b, b1v.y);
        ffma2(O1[4], e1b, b2v.x); ffma2(O1[5], e1b, b2v.y);
        ffma2(O1[6], e1b, b3v.x); ffma2(O1[7], e1b, b3v.y);
    }

    float dens0 = expf(fminf(fmaxf(unpk(O0[7]).y, -15.0f), 15.0f));
    float dens1 = expf(fminf(fmaxf(unpk(O1[7]).y, -15.0f), 15.0f));
    int ray0 = n0 >> 6;
    int ray1 = n1 >> 6;

    // ============== Layer 3: ci[31] @ Wc1[31][64] ==============
    unsigned long long B0[32], B1[32];
    #pragma unroll
    for (int p = 0; p < 32; p++) { B0[p] = 0ull; B1[p] = 0ull; }

    // k = 0..15 : SH encodings
    #pragma unroll 4
    for (int k = 0; k < 16; k++) {
        unsigned long long c0 = dup2(__ldg(g_enc + ray0 * 16 + k));
        unsigned long long c1 = dup2(__ldg(g_enc + ray1 * 16 + k));
        const ulonglong2* w = (const ulonglong2*)(sW + SC1_OFF + k * 64);
        #pragma unroll
        for (int jj = 0; jj < 16; jj++) {
            ulonglong2 ww = w[jj];
            ffma2(B0[2*jj],   c0, ww.x);
            ffma2(B0[2*jj+1], c0, ww.y);
            ffma2(B1[2*jj],   c1, ww.x);
            ffma2(B1[2*jj+1], c1, ww.y);
        }
    }
    // k = 16..30 : geo = O[0..14] (raw, no relu)
    #pragma unroll
    for (int p = 0; p < 8; p++) {
        float2 o0 = unpk(O0[p]);
        float2 o1 = unpk(O1[p]);
        // geo index 2p  -> k = 16 + 2p
        {
            unsigned long long c0 = dup2(o0.x);
            unsigned long long c1 = dup2(o1.x);
            const ulonglong2* w = (const ulonglong2*)(sW + SC1_OFF + (16 + 2*p) * 64);
            #pragma unroll
            for (int jj = 0; jj < 16; jj++) {
                ulonglong2 ww = w[jj];
                ffma2(B0[2*jj],   c0, ww.x);
                ffma2(B0[2*jj+1], c0, ww.y);
                ffma2(B1[2*jj],   c1, ww.x);
                ffma2(B1[2*jj+1], c1, ww.y);
            }
        }
        // geo index 2p+1 -> k = 17 + 2p (skip when 2p+1 == 15, i.e. p == 7)
        if (p < 7) {
            unsigned long long c0 = dup2(o0.y);
            unsigned long long c1 = dup2(o1.y);
            const ulonglong2* w = (const ulonglong2*)(sW + SC1_OFF + (17 + 2*p) * 64);
            #pragma unroll
            for (int jj = 0; jj < 16; jj++) {
                ulonglong2 ww = w[jj];
                ffma2(B0[2*jj],   c0, ww.x);
                ffma2(B0[2*jj+1], c0, ww.y);
                ffma2(B1[2*jj],   c1, ww.x);
                ffma2(B1[2*jj+1], c1, ww.y);
            }
        }
    }

    // relu + stage to smem scratch
    #pragma unroll
    for (int p = 0; p < 32; p++) {
        float2 b0 = unpk(B0[p]);
        float2 b1 = unpk(B1[p]);
        hb0[(2*p)   * 128 + tid] = fmaxf(b0.x, 0.0f);
        hb0[(2*p+1) * 128 + tid] = fmaxf(b0.y, 0.0f);
        hb1[(2*p)   * 128 + tid] = fmaxf(b1.x, 0.0f);
        hb1[(2*p+1) * 128 + tid] = fmaxf(b1.y, 0.0f);
    }

    // ============== Layer 4: h3 @ Wc2[64][64] ==============
    #pragma unroll
    for (int p = 0; p < 32; p++) { B0[p] = 0ull; B1[p] = 0ull; }

    #pragma unroll 4
    for (int k = 0; k < 64; k++) {
        unsigned long long h0 = dup2(hb0[k * 128 + tid]);
        unsigned long long h1 = dup2(hb1[k * 128 + tid]);
        const ulonglong2* w = (const ulonglong2*)(sW + SC2_OFF + k * 64);
        #pragma unroll
        for (int jj = 0; jj < 16; jj++) {
            ulonglong2 ww = w[jj];
            ffma2(B0[2*jj],   h0, ww.x);
            ffma2(B0[2*jj+1], h0, ww.y);
            ffma2(B1[2*jj],   h1, ww.x);
            ffma2(B1[2*jj+1], h1, ww.y);
        }
    }

    // ============== Layer 5: relu(B) @ Wc3[64][3] -> rgb ==============
    float r00 = 0.f, r01 = 0.f, r02 = 0.f;
    float r10 = 0.f, r11 = 0.f, r12 = 0.f;
    #pragma unroll 8
    for (int p = 0; p < 32; p++) {
        float2 b0 = unpk(B0[p]);
        float2 b1 = unpk(B1[p]);
        float h0a = fmaxf(b0.x, 0.0f), h0b = fmaxf(b0.y, 0.0f);
        float h1a = fmaxf(b1.x, 0.0f), h1b = fmaxf(b1.y, 0.0f);
        const float* wa = sW + SC3_OFF + (2*p) * 3;
        float w0 = wa[0], w1 = wa[1], w2 = wa[2];
        float w3 = wa[3], w4 = wa[4], w5 = wa[5];
        r00 += h0a * w0; r01 += h0a * w1; r02 += h0a * w2;
        r00 += h0b * w3; r01 += h0b * w4; r02 += h0b * w5;
        r10 += h1a * w0; r11 += h1a * w1; r12 += h1a * w2;
        r10 += h1b * w3; r11 += h1b * w4; r12 += h1b * w5;
    }

    float4 out0, out1;
    out0.x = 1.0f / (1.0f + expf(-r00));
    out0.y = 1.0f / (1.0f + expf(-r01));
    out0.z = 1.0f / (1.0f + expf(-r02));
    out0.w = dens0;
    out1.x = 1.0f / (1.0f + expf(-r10));
    out1.y = 1.0f / (1.0f + expf(-r11));
    out1.z = 1.0f / (1.0f + expf(-r12));
    out1.w = dens1;
    ((float4*)out)[n0] = out0;
    ((float4*)out)[n1] = out1;
}

// ---------------------------------------------------------------------------
// Launch
// ---------------------------------------------------------------------------
extern "C" void kernel_launch(void* const* d_in, const int* in_sizes, int n_in,
                              void* d_out, int out_size)
{
    const float* pts   = (const float*)d_in[0];
    const float* dirs  = (const float*)d_in[1];
    const float* ts    = (const float*)d_in[2];
    const float* yl[6], *yh[6];
    for (int i = 0; i < 6; i++) {
        yl[i] = (const float*)d_in[3 + 2*i];
        yh[i] = (const float*)d_in[4 + 2*i];
    }
    const float* Ws1 = (const float*)d_in[15];
    const float* Ws2 = (const float*)d_in[16];
    const float* Wc1 = (const float*)d_in[17];
    const float* Wc2 = (const float*)d_in[18];
    const float* Wc3 = (const float*)d_in[19];
    float* out = (float*)d_out;

    static bool attr_done = false;
    if (!attr_done) {
        cudaFuncSetAttribute(gather_kernel,
                             cudaFuncAttributeMaxDynamicSharedMemorySize,
                             GATHER_SMEM);
        cudaFuncSetAttribute(mlp_kernel,
                             cudaFuncAttributeMaxDynamicSharedMemorySize,
                             MLP_SMEM);
        attr_done = true;
    }

    expand_kernel<<<(N_COARSE + 7) / 8, 256>>>(
        yl[0], yh[0], yl[1], yh[1], yl[2], yh[2],
        yl[3], yh[3], yl[4], yh[4], yl[5], yh[5]);

    sh_kernel<<<R_RAYS / 256, 256>>>(dirs);

    gather_kernel<<<NSAMP / 128, 128, GATHER_SMEM>>>(pts, ts);

    mlp_kernel<<<NSAMP / 256, 128, MLP_SMEM>>>(Ws1, Ws2, Wc1, Wc2, Wc3, out);
}

// round 6
// speedup vs baseline: 1.6020x; 1.0284x over previous
#include <cuda_runtime.h>
#include <math.h>

// ---------------------------------------------------------------------------
// Problem constants
// ---------------------------------------------------------------------------
#define R_RAYS   8192
#define S_SAMP   64
#define NSAMP    (R_RAYS * S_SAMP)      // 524288
#define C_FEAT   32

// Combos (j,k) indexing p4 = (x,y,z,t)
__device__ __constant__ int d_J[6] = {0,0,0,1,1,2};
__device__ __constant__ int d_K[6] = {1,2,3,2,3,3};

// Coarse plane widths (h = 64 for all)
__device__ __constant__ int d_cw[6]    = {64,64,50,64,50,50};
__device__ __constant__ int d_cbase[6] = {0,4096,8192,11392,15488,18688};
#define N_COARSE 21888

// Fine plane widths (H = 128 for all), W = 2w
__device__ __constant__ int d_fw[6]    = {128,128,100,128,100,100};
__device__ __constant__ int d_fbase[6] = {0,16384,32768,45568,61952,74752};
#define N_FINE 87552

// ---------------------------------------------------------------------------
// Scratch (device globals; no runtime allocation allowed)
// ---------------------------------------------------------------------------
__device__ float g_hi[N_FINE * C_FEAT];       // 11.2 MB  [texel][c]
__device__ float g_lo[N_FINE * C_FEAT];       // 11.2 MB
__device__ float g_feats[64 * NSAMP];         // 134 MB, feature-major [f][n]
__device__ float g_enc[R_RAYS * 16];          // SH encodings per ray

// ---------------------------------------------------------------------------
// f32x2 packed-FMA helpers (Blackwell FFMA2 — only reachable via PTX)
// ---------------------------------------------------------------------------
__device__ __forceinline__ unsigned long long dup2(float f) {
    unsigned long long r;
    asm("mov.b64 %0, {%1, %1};" : "=l"(r) : "r"(__float_as_uint(f)));
    return r;
}
__device__ __forceinline__ void ffma2(unsigned long long& d,
                                      unsigned long long a,
                                      unsigned long long b) {
    asm("fma.rn.f32x2 %0, %1, %2, %0;" : "+l"(d) : "l"(a), "l"(b));
}
__device__ __forceinline__ float2 unpk(unsigned long long v) {
    unsigned lo, hi;
    asm("mov.b64 {%0, %1}, %2;" : "=r"(lo), "=r"(hi) : "l"(v));
    float2 r;
    r.x = __uint_as_float(lo);
    r.y = __uint_as_float(hi);
    return r;
}

// ---------------------------------------------------------------------------
// Kernel 1: expand (yl, yh) -> hi / lo fine planes, channel-fastest layout
// ---------------------------------------------------------------------------
__global__ void expand_kernel(
    const float* __restrict__ yl0, const float* __restrict__ yh0,
    const float* __restrict__ yl1, const float* __restrict__ yh1,
    const float* __restrict__ yl2, const float* __restrict__ yh2,
    const float* __restrict__ yl3, const float* __restrict__ yh3,
    const float* __restrict__ yl4, const float* __restrict__ yh4,
    const float* __restrict__ yl5, const float* __restrict__ yh5)
{
    const float* yls[6] = {yl0, yl1, yl2, yl3, yl4, yl5};
    const float* yhs[6] = {yh0, yh1, yh2, yh3, yh4, yh5};

    int warpIdx = (blockIdx.x * blockDim.x + threadIdx.x) >> 5;
    int lane    = threadIdx.x & 31;
    if (warpIdx >= N_COARSE) return;

    int p = 0;
    #pragma unroll
    for (int q = 1; q < 6; q++) if (warpIdx >= d_cbase[q]) p = q;

    int local = warpIdx - d_cbase[p];
    int w  = d_cw[p];
    int cy = local / w;
    int cx = local - cy * w;
    int hw = 64 * w;

    const float* yl = yls[p];
    const float* yh = yhs[p];

    float a  = yl[lane * hw + cy * w + cx];
    const float* yhc = yh + (size_t)lane * 3 * hw + cy * w + cx;
    float lh = yhc[0];
    float hl = yhc[hw];
    float hh = yhc[2 * hw];

    int W    = 2 * w;
    int base = d_fbase[p] + (2 * cy) * W + 2 * cx;
    int i00 = base * 32 + lane;
    int i01 = i00 + 32;
    int i10 = (base + W) * 32 + lane;
    int i11 = i10 + 32;

    g_hi[i00] = 0.5f * (a + lh + hl + hh);
    g_hi[i01] = 0.5f * (a + lh - hl - hh);
    g_hi[i10] = 0.5f * (a - lh + hl - hh);
    g_hi[i11] = 0.5f * (a - lh - hl + hh);

    float lv = 0.5f * a;
    g_lo[i00] = lv; g_lo[i01] = lv; g_lo[i10] = lv; g_lo[i11] = lv;
}

// ---------------------------------------------------------------------------
// Kernel 2: SH degree-4 encoding per ray
// ---------------------------------------------------------------------------
__global__ void sh_kernel(const float* __restrict__ dirs)
{
    int r = blockIdx.x * blockDim.x + threadIdx.x;
    if (r >= R_RAYS) return;
    float dx = dirs[3*r], dy = dirs[3*r+1], dz = dirs[3*r+2];
    float nrm = sqrtf(dx*dx + dy*dy + dz*dz);
    float x = dx / nrm, y = dy / nrm, z = dz / nrm;
    float xx = x*x, yy = y*y, zz = z*z;

    float* e = g_enc + r * 16;
    e[0]  = 0.28209479177387814f;
    e[1]  = -0.4886025119029199f * y;
    e[2]  =  0.4886025119029199f * z;
    e[3]  = -0.4886025119029199f * x;
    e[4]  =  1.0925484305920792f * x * y;
    e[5]  = -1.0925484305920792f * y * z;
    e[6]  =  0.31539156525252005f * (3.0f * zz - 1.0f);
    e[7]  = -1.0925484305920792f * x * z;
    e[8]  =  0.5462742152960396f * (xx - yy);
    e[9]  = -0.5900435899266435f * y * (3.0f * xx - yy);
    e[10] =  2.890611442640554f * x * y * z;
    e[11] = -0.4570457994644658f * y * (5.0f * zz - 1.0f);
    e[12] =  0.3731763325901154f * z * (5.0f * zz - 3.0f);
    e[13] = -0.4570457994644658f * x * (5.0f * zz - 1.0f);
    e[14] =  1.445305721320277f * z * (xx - yy);
    e[15] = -0.5900435899266435f * x * (xx - 3.0f * yy);
}

// ---------------------------------------------------------------------------
// Kernel 3: gather + bilerp + 6-way product -> g_feats (feature-major)
// ---------------------------------------------------------------------------
#define GW_AW    1152
#define GW_TILE  (64 * 33)
#define GW_WORDS (GW_AW + GW_TILE)
#define GATHER_SMEM (4 * GW_WORDS * 4)

__global__ void gather_kernel(const float* __restrict__ pts,
                              const float* __restrict__ tstamps)
{
    extern __shared__ float smem[];
    int warp = threadIdx.x >> 5;
    int lane = threadIdx.x & 31;

    float* aw   = smem + warp * GW_WORDS;
    float* tile = aw + GW_AW;

    int n0 = (blockIdx.x * 4 + warp) * 32;
    int n  = n0 + lane;

    float p4[4];
    p4[0] = pts[3*n + 0];
    p4[1] = pts[3*n + 1];
    p4[2] = pts[3*n + 2];
    p4[3] = tstamps[n >> 6] * 2.0f - 1.0f;

    #pragma unroll
    for (int m = 0; m < 6; m++) {
        float cy_ = p4[d_J[m]];
        float cx_ = p4[d_K[m]];
        int W = d_fw[m];

        float y = (cy_ + 1.0f) * 0.5f * 127.0f;
        float x = (cx_ + 1.0f) * 0.5f * (float)(W - 1);

        float fy = floorf(y);
        int y0 = (int)fminf(fmaxf(fy, 0.0f), 127.0f);
        float wy = fminf(fmaxf(y - (float)y0, 0.0f), 1.0f);
        int y1 = min(y0 + 1, 127);

        float fx = floorf(x);
        int x0 = (int)fminf(fmaxf(fx, 0.0f), (float)(W - 1));
        float wx = fminf(fmaxf(x - (float)x0, 0.0f), 1.0f);
        int x1 = min(x0 + 1, W - 1);

        int b = d_fbase[m];
        int a00 = (b + y0 * W + x0) * 32;
        int a01 = (b + y0 * W + x1) * 32;
        int a10 = (b + y1 * W + x0) * 32;
        int a11 = (b + y1 * W + x1) * 32;

        float* s = aw + lane * 36 + m * 6;
        ((int*)s)[0] = a00;
        ((int*)s)[1] = a01;
        ((int*)s)[2] = a10;
        ((int*)s)[3] = a11;
        s[4] = wy;
        s[5] = wx;
    }
    __syncwarp();

    for (int i = 0; i < 32; i++) {
        float ah = 1.0f, al = 1.0f;
        #pragma unroll
        for (int m = 0; m < 6; m++) {
            const float* s = aw + i * 36 + m * 6;
            int a00 = ((const int*)s)[0];
            int a01 = ((const int*)s)[1];
            int a10 = ((const int*)s)[2];
            int a11 = ((const int*)s)[3];
            float wy = s[4];
            float wx = s[5];
            float w00 = (1.0f - wy) * (1.0f - wx);
            float w01 = (1.0f - wy) * wx;
            float w10 = wy * (1.0f - wx);
            float w11 = wy * wx;

            float vh = w00 * __ldg(g_hi + a00 + lane)
                     + w01 * __ldg(g_hi + a01 + lane)
                     + w10 * __ldg(g_hi + a10 + lane)
                     + w11 * __ldg(g_hi + a11 + lane);
            float vl = w00 * __ldg(g_lo + a00 + lane)
                     + w01 * __ldg(g_lo + a01 + lane)
                     + w10 * __ldg(g_lo + a10 + lane)
                     + w11 * __ldg(g_lo + a11 + lane);
            ah *= vh;
            al *= vl;
        }
        tile[lane * 33 + i]        = ah;
        tile[(32 + lane) * 33 + i] = al;
    }
    __syncwarp();

    #pragma unroll 8
    for (int r = 0; r < 64; r++) {
        g_feats[r * NSAMP + n0 + lane] = tile[r * 33 + lane];
    }
}

// ---------------------------------------------------------------------------
// Kernel 4: fused MLP — 2 samples per thread, f32x2 packed FMA.
// Smem (floats): weights [0,11392), feats/hb region [11392, 27776),
//                enc [27776, 27840).  Total 111360 B -> 2 blocks/SM.
// The 16384-float region first holds the staged feats tile [64 k][256 cols],
// then is overwritten by L3 activations.  Thread T only reads feats columns
// {T, T+128} and its hb writes land only in those same columns, so per-thread
// program order guarantees safety (no extra barrier needed).
// ---------------------------------------------------------------------------
#define SW1_OFF   0
#define SW2_OFF   4096
#define SC1_OFF   5120
#define SC2_OFF   7104
#define SC3_OFF   11200
#define SW_TOTAL  11392
#define FEATS_OFF SW_TOTAL               // also hb region
#define ENC_OFF   (SW_TOTAL + 16384)
#define MLP_SMEM  ((SW_TOTAL + 16384 + 64) * 4)   // 111360 bytes

__global__ void __launch_bounds__(128) mlp_kernel(
    const float* __restrict__ Ws1, const float* __restrict__ Ws2,
    const float* __restrict__ Wc1, const float* __restrict__ Wc2,
    const float* __restrict__ Wc3, float* __restrict__ out)
{
    extern __shared__ __align__(16) float sm[];
    float* sW      = sm;
    float* feats_s = sm + FEATS_OFF;       // [64][256] during L1
    float* hb0     = sm + FEATS_OFF;       // [64][128] after L3 (sample 0)
    float* hb1     = hb0 + 64 * 128;       // [64][128] (sample 1)
    float* enc_s   = sm + ENC_OFF;         // [4 rays][16]

    int tid  = threadIdx.x;
    int base = blockIdx.x * 256;

    // ---- cooperative staging: weights + feats tile + enc ----
    for (int i = tid; i < 4096; i += 128) sW[SW1_OFF + i] = Ws1[i];
    for (int i = tid; i < 1024; i += 128) sW[SW2_OFF + i] = Ws2[i];
    for (int i = tid; i < 1984; i += 128) sW[SC1_OFF + i] = Wc1[i];
    for (int i = tid; i < 4096; i += 128) sW[SC2_OFF + i] = Wc2[i];
    for (int i = tid; i <  192; i += 128) sW[SC3_OFF + i] = Wc3[i];

    // feats: 64 rows x 256 cols, 4096 float4s, fully coalesced
    {
        float4* dst = (float4*)feats_s;
        #pragma unroll 8
        for (int i = tid; i < 4096; i += 128) {
            int k  = i >> 6;
            int c4 = i & 63;
            dst[i] = *(const float4*)(g_feats + (size_t)k * NSAMP + base + 4 * c4);
        }
    }
    if (tid < 64) enc_s[tid] = g_enc[(base >> 6) * 16 + tid];
    __syncthreads();

    int n0 = base + tid;                   // sample 0
    int n1 = n0 + 128;                     // sample 1

    // ============== Layer 1: feats[64] @ Wsig1[64][64] ==============
    unsigned long long A0[32], A1[32];     // A*[p] packs neurons (2p, 2p+1)
    #pragma unroll
    for (int p = 0; p < 32; p++) { A0[p] = 0ull; A1[p] = 0ull; }

    #pragma unroll 4
    for (int k = 0; k < 64; k++) {
        unsigned long long f0 = dup2(feats_s[k * 256 + tid]);
        unsigned long long f1 = dup2(feats_s[k * 256 + tid + 128]);
        const ulonglong2* w = (const ulonglong2*)(sW + SW1_OFF + k * 64);
        #pragma unroll
        for (int jj = 0; jj < 16; jj++) {
            ulonglong2 ww = w[jj];
            ffma2(A0[2*jj],   f0, ww.x);
            ffma2(A0[2*jj+1], f0, ww.y);
            ffma2(A1[2*jj],   f1, ww.x);
            ffma2(A1[2*jj+1], f1, ww.y);
        }
    }

    // ============== Layer 2: relu(A) @ Wsig2[64][16] ==============
    unsigned long long O0[8], O1[8];       // O*[q] packs outputs (2q, 2q+1)
    #pragma unroll
    for (int q = 0; q < 8; q++) { O0[q] = 0ull; O1[q] = 0ull; }

    #pragma unroll 4
    for (int p = 0; p < 32; p++) {
        float2 a0 = unpk(A0[p]);
        float2 a1 = unpk(A1[p]);
        unsigned long long e0a = dup2(fmaxf(a0.x, 0.0f));
        unsigned long long e0b = dup2(fmaxf(a0.y, 0.0f));
        unsigned long long e1a = dup2(fmaxf(a1.x, 0.0f));
        unsigned long long e1b = dup2(fmaxf(a1.y, 0.0f));
        const ulonglong2* ra = (const ulonglong2*)(sW + SW2_OFF + (2*p)   * 16);
        const ulonglong2* rb = (const ulonglong2*)(sW + SW2_OFF + (2*p+1) * 16);
        ulonglong2 a0v = ra[0], a1v = ra[1], a2v = ra[2], a3v = ra[3];
        ffma2(O0[0], e0a, a0v.x); ffma2(O0[1], e0a, a0v.y);
        ffma2(O0[2], e0a, a1v.x); ffma2(O0[3], e0a, a1v.y);
        ffma2(O0[4], e0a, a2v.x); ffma2(O0[5], e0a, a2v.y);
        ffma2(O0[6], e0a, a3v.x); ffma2(O0[7], e0a, a3v.y);
        ffma2(O1[0], e1a, a0v.x); ffma2(O1[1], e1a, a0v.y);
        ffma2(O1[2], e1a, a1v.x); ffma2(O1[3], e1a, a1v.y);
        ffma2(O1[4], e1a, a2v.x); ffma2(O1[5], e1a, a2v.y);
        ffma2(O1[6], e1a, a3v.x); ffma2(O1[7], e1a, a3v.y);
        ulonglong2 b0v = rb[0], b1v = rb[1], b2v = rb[2], b3v = rb[3];
        ffma2(O0[0], e0b, b0v.x); ffma2(O0[1], e0b, b0v.y);
        ffma2(O0[2], e0b, b1v.x); ffma2(O0[3], e0b, b1v.y);
        ffma2(O0[4], e0b, b2v.x); ffma2(O0[5], e0b, b2v.y);
        ffma2(O0[6], e0b, b3v.x); ffma2(O0[7], e0b, b3v.y);
        ffma2(O1[0], e1b, b0v.x); ffma2(O1[1], e1b, b0v.y);
        ffma2(O1[2], e1b, b1v.x); ffma2(O1[3], e1b, b1v.y);
        ffma2(O1[4], e1b, b2v.x); ffma2(O1[5], e1b, b2v.y);
        ffma2(O1[6], e1b, b3v.x); ffma2(O1[7], e1b, b3v.y);
    }

    float dens0 = expf(fminf(fmaxf(unpk(O0[7]).y, -15.0f), 15.0f));
    float dens1 = expf(fminf(fmaxf(unpk(O1[7]).y, -15.0f), 15.0f));
    int rl0 = tid >> 6;                    // local ray of sample 0 (0..1)
    int rl1 = rl0 + 2;                     // local ray of sample 1 (2..3)

    // ============== Layer 3: ci[31] @ Wc1[31][64] ==============
    unsigned long long B0[32], B1[32];
    #pragma unroll
    for (int p = 0; p < 32; p++) { B0[p] = 0ull; B1[p] = 0ull; }

    // k = 0..15 : SH encodings (from smem, warp-uniform broadcast)
    #pragma unroll 4
    for (int k = 0; k < 16; k++) {
        unsigned long long c0 = dup2(enc_s[rl0 * 16 + k]);
        unsigned long long c1 = dup2(enc_s[rl1 * 16 + k]);
        const ulonglong2* w = (const ulonglong2*)(sW + SC1_OFF + k * 64);
        #pragma unroll
        for (int jj = 0; jj < 16; jj++) {
            ulonglong2 ww = w[jj];
            ffma2(B0[2*jj],   c0, ww.x);
            ffma2(B0[2*jj+1], c0, ww.y);
            ffma2(B1[2*jj],   c1, ww.x);
            ffma2(B1[2*jj+1], c1, ww.y);
        }
    }
    // k = 16..30 : geo = O[0..14] (raw, no relu)
    #pragma unroll
    for (int p = 0; p < 8; p++) {
        float2 o0 = unpk(O0[p]);
        float2 o1 = unpk(O1[p]);
        {
            unsigned long long c0 = dup2(o0.x);
            unsigned long long c1 = dup2(o1.x);
            const ulonglong2* w = (const ulonglong2*)(sW + SC1_OFF + (16 + 2*p) * 64);
            #pragma unroll
            for (int jj = 0; jj < 16; jj++) {
                ulonglong2 ww = w[jj];
                ffma2(B0[2*jj],   c0, ww.x);
                ffma2(B0[2*jj+1], c0, ww.y);
                ffma2(B1[2*jj],   c1, ww.x);
                ffma2(B1[2*jj+1], c1, ww.y);
            }
        }
        if (p < 7) {
            unsigned long long c0 = dup2(o0.y);
            unsigned long long c1 = dup2(o1.y);
            const ulonglong2* w = (const ulonglong2*)(sW + SC1_OFF + (17 + 2*p) * 64);
            #pragma unroll
            for (int jj = 0; jj < 16; jj++) {
                ulonglong2 ww = w[jj];
                ffma2(B0[2*jj],   c0, ww.x);
                ffma2(B0[2*jj+1], c0, ww.y);
                ffma2(B1[2*jj],   c1, ww.x);
                ffma2(B1[2*jj+1], c1, ww.y);
            }
        }
    }

    // relu + stage to smem scratch (overwrites this thread's feats columns only)
    #pragma unroll
    for (int p = 0; p < 32; p++) {
        float2 b0 = unpk(B0[p]);
        float2 b1 = unpk(B1[p]);
        hb0[(2*p)   * 128 + tid] = fmaxf(b0.x, 0.0f);
        hb0[(2*p+1) * 128 + tid] = fmaxf(b0.y, 0.0f);
        hb1[(2*p)   * 128 + tid] = fmaxf(b1.x, 0.0f);
        hb1[(2*p+1) * 128 + tid] = fmaxf(b1.y, 0.0f);
    }

    // ============== Layer 4: h3 @ Wc2[64][64] ==============
    #pragma unroll
    for (int p = 0; p < 32; p++) { B0[p] = 0ull; B1[p] = 0ull; }

    #pragma unroll 4
    for (int k = 0; k < 64; k++) {
        unsigned long long h0 = dup2(hb0[k * 128 + tid]);
        unsigned long long h1 = dup2(hb1[k * 128 + tid]);
        const ulonglong2* w = (const ulonglong2*)(sW + SC2_OFF + k * 64);
        #pragma unroll
        for (int jj = 0; jj < 16; jj++) {
            ulonglong2 ww = w[jj];
            ffma2(B0[2*jj],   h0, ww.x);
            ffma2(B0[2*jj+1], h0, ww.y);
            ffma2(B1[2*jj],   h1, ww.x);
            ffma2(B1[2*jj+1], h1, ww.y);
        }
    }

    // ============== Layer 5: relu(B) @ Wc3[64][3] -> rgb ==============
    float r00 = 0.f, r01 = 0.f, r02 = 0.f;
    float r10 = 0.f, r11 = 0.f, r12 = 0.f;
    #pragma unroll 8
    for (int p = 0; p < 32; p++) {
        float2 b0 = unpk(B0[p]);
        float2 b1 = unpk(B1[p]);
        float h0a = fmaxf(b0.x, 0.0f), h0b = fmaxf(b0.y, 0.0f);
        float h1a = fmaxf(b1.x, 0.0f), h1b = fmaxf(b1.y, 0.0f);
        const float* wa = sW + SC3_OFF + (2*p) * 3;
        float w0 = wa[0], w1 = wa[1], w2 = wa[2];
        float w3 = wa[3], w4 = wa[4], w5 = wa[5];
        r00 += h0a * w0; r01 += h0a * w1; r02 += h0a * w2;
        r00 += h0b * w3; r01 += h0b * w4; r02 += h0b * w5;
        r10 += h1a * w0; r11 += h1a * w1; r12 += h1a * w2;
        r10 += h1b * w3; r11 += h1b * w4; r12 += h1b * w5;
    }

    float4 out0, out1;
    out0.x = 1.0f / (1.0f + expf(-r00));
    out0.y = 1.0f / (1.0f + expf(-r01));
    out0.z = 1.0f / (1.0f + expf(-r02));
    out0.w = dens0;
    out1.x = 1.0f / (1.0f + expf(-r10));
    out1.y = 1.0f / (1.0f + expf(-r11));
    out1.z = 1.0f / (1.0f + expf(-r12));
    out1.w = dens1;
    ((float4*)out)[n0] = out0;
    ((float4*)out)[n1] = out1;
}

// ---------------------------------------------------------------------------
// Launch
// ---------------------------------------------------------------------------
extern "C" void kernel_launch(void* const* d_in, const int* in_sizes, int n_in,
                              void* d_out, int out_size)
{
    const float* pts   = (const float*)d_in[0];
    const float* dirs  = (const float*)d_in[1];
    const float* ts    = (const float*)d_in[2];
    const float* yl[6], *yh[6];
    for (int i = 0; i < 6; i++) {
        yl[i] = (const float*)d_in[3 + 2*i];
        yh[i] = (const float*)d_in[4 + 2*i];
    }
    const float* Ws1 = (const float*)d_in[15];
    const float* Ws2 = (const float*)d_in[16];
    const float* Wc1 = (const float*)d_in[17];
    const float* Wc2 = (const float*)d_in[18];
    const float* Wc3 = (const float*)d_in[19];
    float* out = (float*)d_out;

    static bool attr_done = false;
    if (!attr_done) {
        cudaFuncSetAttribute(gather_kernel,
                             cudaFuncAttributeMaxDynamicSharedMemorySize,
                             GATHER_SMEM);
        cudaFuncSetAttribute(mlp_kernel,
                             cudaFuncAttributeMaxDynamicSharedMemorySize,
                             MLP_SMEM);
        attr_done = true;
    }

    expand_kernel<<<(N_COARSE + 7) / 8, 256>>>(
        yl[0], yh[0], yl[1], yh[1], yl[2], yh[2],
        yl[3], yh[3], yl[4], yh[4], yl[5], yh[5]);

    sh_kernel<<<R_RAYS / 256, 256>>>(dirs);

    gather_kernel<<<NSAMP / 128, 128, GATHER_SMEM>>>(pts, ts);

    mlp_kernel<<<NSAMP / 256, 128, MLP_SMEM>>>(Ws1, Ws2, Wc1, Wc2, Wc3, out);
}

// round 7
// speedup vs baseline: 2.0188x; 1.2601x over previous
#include <cuda_runtime.h>
#include <math.h>

// ---------------------------------------------------------------------------
// Problem constants
// ---------------------------------------------------------------------------
#define R_RAYS   8192
#define S_SAMP   64
#define NSAMP    (R_RAYS * S_SAMP)      // 524288
#define C_FEAT   32

__device__ __constant__ int d_J[6] = {0,0,0,1,1,2};
__device__ __constant__ int d_K[6] = {1,2,3,2,3,3};

__device__ __constant__ int d_cw[6]    = {64,64,50,64,50,50};
__device__ __constant__ int d_cbase[6] = {0,4096,8192,11392,15488,18688};
#define N_COARSE 21888

__device__ __constant__ int d_fw[6]    = {128,128,100,128,100,100};
__device__ __constant__ int d_fbase[6] = {0,16384,32768,45568,61952,74752};
#define N_FINE 87552

// ---------------------------------------------------------------------------
// Scratch (device globals; no runtime allocation allowed)
// ---------------------------------------------------------------------------
__device__ float g_hi[N_FINE * C_FEAT];
__device__ float g_lo[N_FINE * C_FEAT];
__device__ float g_feats[64 * NSAMP];         // feature-major [f][n]
__device__ float g_enc[R_RAYS * 16];

// ---------------------------------------------------------------------------
// tf32 helpers
// ---------------------------------------------------------------------------
__device__ __forceinline__ unsigned tf32_bits(float x) {
    unsigned u;
    asm("cvt.rna.tf32.f32 %0, %1;" : "=r"(u) : "f"(x));
    return u;
}
__device__ __forceinline__ float tf32_val(float x) {
    return __uint_as_float(tf32_bits(x));
}

__device__ __forceinline__ void mma_tf32(float* d,
    unsigned a0, unsigned a1, unsigned a2, unsigned a3,
    unsigned b0, unsigned b1)
{
    asm volatile(
        "mma.sync.aligned.m16n8k8.row.col.f32.tf32.tf32.f32 "
        "{%0,%1,%2,%3}, {%4,%5,%6,%7}, {%8,%9}, {%0,%1,%2,%3};"
        : "+f"(d[0]), "+f"(d[1]), "+f"(d[2]), "+f"(d[3])
        : "r"(a0), "r"(a1), "r"(a2), "r"(a3), "r"(b0), "r"(b1));
}

// ---------------------------------------------------------------------------
// Kernel 1: expand (yl, yh) -> hi / lo fine planes
// ---------------------------------------------------------------------------
__global__ void expand_kernel(
    const float* __restrict__ yl0, const float* __restrict__ yh0,
    const float* __restrict__ yl1, const float* __restrict__ yh1,
    const float* __restrict__ yl2, const float* __restrict__ yh2,
    const float* __restrict__ yl3, const float* __restrict__ yh3,
    const float* __restrict__ yl4, const float* __restrict__ yh4,
    const float* __restrict__ yl5, const float* __restrict__ yh5)
{
    const float* yls[6] = {yl0, yl1, yl2, yl3, yl4, yl5};
    const float* yhs[6] = {yh0, yh1, yh2, yh3, yh4, yh5};

    int warpIdx = (blockIdx.x * blockDim.x + threadIdx.x) >> 5;
    int lane    = threadIdx.x & 31;
    if (warpIdx >= N_COARSE) return;

    int p = 0;
    #pragma unroll
    for (int q = 1; q < 6; q++) if (warpIdx >= d_cbase[q]) p = q;

    int local = warpIdx - d_cbase[p];
    int w  = d_cw[p];
    int cy = local / w;
    int cx = local - cy * w;
    int hw = 64 * w;

    const float* yl = yls[p];
    const float* yh = yhs[p];

    float a  = yl[lane * hw + cy * w + cx];
    const float* yhc = yh + (size_t)lane * 3 * hw + cy * w + cx;
    float lh = yhc[0];
    float hl = yhc[hw];
    float hh = yhc[2 * hw];

    int W    = 2 * w;
    int base = d_fbase[p] + (2 * cy) * W + 2 * cx;
    int i00 = base * 32 + lane;
    int i01 = i00 + 32;
    int i10 = (base + W) * 32 + lane;
    int i11 = i10 + 32;

    g_hi[i00] = 0.5f * (a + lh + hl + hh);
    g_hi[i01] = 0.5f * (a + lh - hl - hh);
    g_hi[i10] = 0.5f * (a - lh + hl - hh);
    g_hi[i11] = 0.5f * (a - lh - hl + hh);

    float lv = 0.5f * a;
    g_lo[i00] = lv; g_lo[i01] = lv; g_lo[i10] = lv; g_lo[i11] = lv;
}

// ---------------------------------------------------------------------------
// Kernel 2: SH degree-4 encoding per ray
// ---------------------------------------------------------------------------
__global__ void sh_kernel(const float* __restrict__ dirs)
{
    int r = blockIdx.x * blockDim.x + threadIdx.x;
    if (r >= R_RAYS) return;
    float dx = dirs[3*r], dy = dirs[3*r+1], dz = dirs[3*r+2];
    float nrm = sqrtf(dx*dx + dy*dy + dz*dz);
    float x = dx / nrm, y = dy / nrm, z = dz / nrm;
    float xx = x*x, yy = y*y, zz = z*z;

    float* e = g_enc + r * 16;
    e[0]  = 0.28209479177387814f;
    e[1]  = -0.4886025119029199f * y;
    e[2]  =  0.4886025119029199f * z;
    e[3]  = -0.4886025119029199f * x;
    e[4]  =  1.0925484305920792f * x * y;
    e[5]  = -1.0925484305920792f * y * z;
    e[6]  =  0.31539156525252005f * (3.0f * zz - 1.0f);
    e[7]  = -1.0925484305920792f * x * z;
    e[8]  =  0.5462742152960396f * (xx - yy);
    e[9]  = -0.5900435899266435f * y * (3.0f * xx - yy);
    e[10] =  2.890611442640554f * x * y * z;
    e[11] = -0.4570457994644658f * y * (5.0f * zz - 1.0f);
    e[12] =  0.3731763325901154f * z * (5.0f * zz - 3.0f);
    e[13] = -0.4570457994644658f * x * (5.0f * zz - 1.0f);
    e[14] =  1.445305721320277f * z * (xx - yy);
    e[15] = -0.5900435899266435f * x * (xx - 3.0f * yy);
}

// ---------------------------------------------------------------------------
// Kernel 3: gather + bilerp + 6-way product -> g_feats (feature-major)
// ---------------------------------------------------------------------------
#define GW_AW    1152
#define GW_TILE  (64 * 33)
#define GW_WORDS (GW_AW + GW_TILE)
#define GATHER_SMEM (4 * GW_WORDS * 4)

__global__ void gather_kernel(const float* __restrict__ pts,
                              const float* __restrict__ tstamps)
{
    extern __shared__ float smem[];
    int warp = threadIdx.x >> 5;
    int lane = threadIdx.x & 31;

    float* aw   = smem + warp * GW_WORDS;
    float* tile = aw + GW_AW;

    int n0 = (blockIdx.x * 4 + warp) * 32;
    int n  = n0 + lane;

    float p4[4];
    p4[0] = pts[3*n + 0];
    p4[1] = pts[3*n + 1];
    p4[2] = pts[3*n + 2];
    p4[3] = tstamps[n >> 6] * 2.0f - 1.0f;

    #pragma unroll
    for (int m = 0; m < 6; m++) {
        float cy_ = p4[d_J[m]];
        float cx_ = p4[d_K[m]];
        int W = d_fw[m];

        float y = (cy_ + 1.0f) * 0.5f * 127.0f;
        float x = (cx_ + 1.0f) * 0.5f * (float)(W - 1);

        float fy = floorf(y);
        int y0 = (int)fminf(fmaxf(fy, 0.0f), 127.0f);
        float wy = fminf(fmaxf(y - (float)y0, 0.0f), 1.0f);
        int y1 = min(y0 + 1, 127);

        float fx = floorf(x);
        int x0 = (int)fminf(fmaxf(fx, 0.0f), (float)(W - 1));
        float wx = fminf(fmaxf(x - (float)x0, 0.0f), 1.0f);
        int x1 = min(x0 + 1, W - 1);

        int b = d_fbase[m];
        int a00 = (b + y0 * W + x0) * 32;
        int a01 = (b + y0 * W + x1) * 32;
        int a10 = (b + y1 * W + x0) * 32;
        int a11 = (b + y1 * W + x1) * 32;

        float* s = aw + lane * 36 + m * 6;
        ((int*)s)[0] = a00;
        ((int*)s)[1] = a01;
        ((int*)s)[2] = a10;
        ((int*)s)[3] = a11;
        s[4] = wy;
        s[5] = wx;
    }
    __syncwarp();

    for (int i = 0; i < 32; i++) {
        float ah = 1.0f, al = 1.0f;
        #pragma unroll
        for (int m = 0; m < 6; m++) {
            const float* s = aw + i * 36 + m * 6;
            int a00 = ((const int*)s)[0];
            int a01 = ((const int*)s)[1];
            int a10 = ((const int*)s)[2];
            int a11 = ((const int*)s)[3];
            float wy = s[4];
            float wx = s[5];
            float w00 = (1.0f - wy) * (1.0f - wx);
            float w01 = (1.0f - wy) * wx;
            float w10 = wy * (1.0f - wx);
            float w11 = wy * wx;

            float vh = w00 * __ldg(g_hi + a00 + lane)
                     + w01 * __ldg(g_hi + a01 + lane)
                     + w10 * __ldg(g_hi + a10 + lane)
                     + w11 * __ldg(g_hi + a11 + lane);
            float vl = w00 * __ldg(g_lo + a00 + lane)
                     + w01 * __ldg(g_lo + a01 + lane)
                     + w10 * __ldg(g_lo + a10 + lane)
                     + w11 * __ldg(g_lo + a11 + lane);
            ah *= vh;
            al *= vl;
        }
        tile[lane * 33 + i]        = ah;
        tile[(32 + lane) * 33 + i] = al;
    }
    __syncwarp();

    #pragma unroll 8
    for (int r = 0; r < 64; r++) {
        g_feats[r * NSAMP + n0 + lane] = tile[r * 33 + lane];
    }
}

// ---------------------------------------------------------------------------
// Kernel 4: tensor-core MLP (3xTF32 mma.sync), 128 samples / block.
//
// smem float offsets:
//   W1B 4608 @0       W1S @4608    (Wsig1 [64][72])
//   W2B 1536 @9216    W2S @10752   (Wsig2 [64][24])
//   C1B 2304 @12288   C1S @14592   (Wc1   [32][72], row31 zero)
//   C2B 4608 @16896   C2S @21504   (Wc2   [64][72])
//   C3  192  @26112   ENC 32 @26304  DENS 128 @26336
//   ACT_A @26496 [64][136]    ACT_B @35200 [64][136]
//   total 43904 floats = 175616 B
// Activation layout: act[k][136 + s] (k = neuron/input index, s = sample).
// Stride 136 -> mma fragment loads are bank-conflict-free (bank = 8k + s).
// ---------------------------------------------------------------------------
#define O_W1B   0
#define O_W1S   4608
#define O_W2B   9216
#define O_W2S   10752
#define O_C1B   12288
#define O_C1S   14592
#define O_C2B   16896
#define O_C2S   21504
#define O_C3    26112
#define O_ENC   26304
#define O_DENS  26336
#define O_ACTA  26496
#define O_ACTB  35200
#define MLP_SMEM (43904 * 4)

// GEMM: D[128 samples x 8*NT neurons] = act(K x s) * W(K x n), 3xTF32.
// Warp w owns sample rows [32w, 32w+32) as two 16-row m-tiles.
template<int NK, int NT>
__device__ __forceinline__ void gemm3x(const float* __restrict__ act,
                                       const float* __restrict__ wb,
                                       const float* __restrict__ ws,
                                       int wstr, int lane, int warp,
                                       float (&d)[2][NT][4])
{
    #pragma unroll
    for (int mt = 0; mt < 2; mt++)
        #pragma unroll
        for (int nt = 0; nt < NT; nt++)
            #pragma unroll
            for (int r = 0; r < 4; r++) d[mt][nt][r] = 0.0f;

    const int srow = warp * 32 + (lane >> 2);   // sample row (a-frag)
    const int kcol = lane & 3;                  // k within k-step
    const int ncol = lane >> 2;                 // n within n-tile (b-frag)

    #pragma unroll
    for (int kk = 0; kk < NK; kk++) {
        unsigned ab[2][4], as[2][4];
        #pragma unroll
        for (int mt = 0; mt < 2; mt++) {
            const float* ap = act + (kk * 8 + kcol) * 136 + srow + mt * 16;
            float r0 = ap[0];
            float r1 = ap[8];
            float r2 = ap[4 * 136];
            float r3 = ap[4 * 136 + 8];
            ab[mt][0] = tf32_bits(r0);
            ab[mt][1] = tf32_bits(r1);
            ab[mt][2] = tf32_bits(r2);
            ab[mt][3] = tf32_bits(r3);
            as[mt][0] = tf32_bits(r0 - __uint_as_float(ab[mt][0]));
            as[mt][1] = tf32_bits(r1 - __uint_as_float(ab[mt][1]));
            as[mt][2] = tf32_bits(r2 - __uint_as_float(ab[mt][2]));
            as[mt][3] = tf32_bits(r3 - __uint_as_float(ab[mt][3]));
        }
        const float* wpb = wb + (kk * 8 + kcol) * wstr + ncol;
        const float* wps = ws + (kk * 8 + kcol) * wstr + ncol;
        #pragma unroll
        for (int nt = 0; nt < NT; nt++) {
            unsigned bb0 = __float_as_uint(wpb[nt * 8]);
            unsigned bb1 = __float_as_uint(wpb[4 * wstr + nt * 8]);
            unsigned bs0 = __float_as_uint(wps[nt * 8]);
            unsigned bs1 = __float_as_uint(wps[4 * wstr + nt * 8]);
            #pragma unroll
            for (int mt = 0; mt < 2; mt++) {
                mma_tf32(d[mt][nt], ab[mt][0], ab[mt][1], ab[mt][2], ab[mt][3], bb0, bb1);
                mma_tf32(d[mt][nt], as[mt][0], as[mt][1], as[mt][2], as[mt][3], bb0, bb1);
                mma_tf32(d[mt][nt], ab[mt][0], ab[mt][1], ab[mt][2], ab[mt][3], bs0, bs1);
            }
        }
    }
}

// store D with relu, transposed into act layout [n][136 + s]
template<int NT>
__device__ __forceinline__ void store_relu(float* __restrict__ dst,
                                           int lane, int warp,
                                           float (&d)[2][NT][4])
{
    int s0 = warp * 32 + (lane >> 2);
    int nb = 2 * (lane & 3);
    #pragma unroll
    for (int mt = 0; mt < 2; mt++) {
        int s = s0 + mt * 16;
        #pragma unroll
        for (int nt = 0; nt < NT; nt++) {
            int n = nt * 8 + nb;
            dst[n * 136 + s]         = fmaxf(d[mt][nt][0], 0.0f);
            dst[(n + 1) * 136 + s]   = fmaxf(d[mt][nt][1], 0.0f);
            dst[n * 136 + s + 8]     = fmaxf(d[mt][nt][2], 0.0f);
            dst[(n + 1) * 136 + s + 8] = fmaxf(d[mt][nt][3], 0.0f);
        }
    }
}

__global__ void __launch_bounds__(128) mlp_kernel(
    const float* __restrict__ Ws1, const float* __restrict__ Ws2,
    const float* __restrict__ Wc1, const float* __restrict__ Wc2,
    const float* __restrict__ Wc3, float* __restrict__ out)
{
    extern __shared__ __align__(16) float sm[];
    const int tid  = threadIdx.x;
    const int lane = tid & 31;
    const int warp = tid >> 5;
    const int base = blockIdx.x * 128;

    // ---- stage weights (tf32 big/small split) ----
    for (int i = tid; i < 4096; i += 128) {
        int k = i >> 6, n = i & 63;
        float w = Ws1[i];
        float b = tf32_val(w);
        sm[O_W1B + k * 72 + n] = b;
        sm[O_W1S + k * 72 + n] = tf32_val(w - b);
        float w2 = Wc2[i];
        float b2 = tf32_val(w2);
        sm[O_C2B + k * 72 + n] = b2;
        sm[O_C2S + k * 72 + n] = tf32_val(w2 - b2);
    }
    for (int i = tid; i < 1024; i += 128) {
        int k = i >> 4, n = i & 15;
        float w = Ws2[i];
        float b = tf32_val(w);
        sm[O_W2B + k * 24 + n] = b;
        sm[O_W2S + k * 24 + n] = tf32_val(w - b);
    }
    for (int i = tid; i < 1984; i += 128) {
        int k = i >> 6, n = i & 63;
        float w = Wc1[i];
        float b = tf32_val(w);
        sm[O_C1B + k * 72 + n] = b;
        sm[O_C1S + k * 72 + n] = tf32_val(w - b);
    }
    if (tid < 72) {                         // zero pad row 31 of C1
        sm[O_C1B + 31 * 72 + tid] = 0.0f;
        sm[O_C1S + 31 * 72 + tid] = 0.0f;
    }
    for (int i = tid; i < 192; i += 128) sm[O_C3 + i] = Wc3[i];
    if (tid < 32) sm[O_ENC + tid] = g_enc[((base >> 6) + (tid >> 4)) * 16 + (tid & 15)];

    // ---- stage feats tile: [64 k][128 s], coalesced float4 ----
    {
        #pragma unroll 4
        for (int i = tid; i < 2048; i += 128) {
            int k  = i >> 5;
            int c4 = i & 31;
            *(float4*)(sm + O_ACTA + k * 136 + 4 * c4) =
                *(const float4*)(g_feats + (size_t)k * NSAMP + base + 4 * c4);
        }
    }
    __syncthreads();

    // ============ L1: feats[64] @ Wsig1 -> relu -> ACT_B ============
    {
        float d[2][8][4];
        gemm3x<8, 8>(sm + O_ACTA, sm + O_W1B, sm + O_W1S, 72, lane, warp, d);
        __syncthreads();                    // all reads of ACT_A done
        store_relu<8>(sm + O_ACTB, lane, warp, d);
        // fill SC1 input rows 0..15 (SH enc) and row 31 (zero) in ACT_A
        for (int i = tid; i < 2048; i += 128) {
            int j = i >> 7, s = i & 127;
            sm[O_ACTA + j * 136 + s] = sm[O_ENC + (s >> 6) * 16 + j];
        }
        sm[O_ACTA + 31 * 136 + tid] = 0.0f;
        __syncthreads();
    }

    // ============ L2: h @ Wsig2 -> geo rows 16..30 of ACT_A, density ============
    {
        float d[2][2][4];
        gemm3x<8, 2>(sm + O_ACTB, sm + O_W2B, sm + O_W2S, 24, lane, warp, d);
        int s0 = warp * 32 + (lane >> 2);
        int nb = 2 * (lane & 3);
        #pragma unroll
        for (int mt = 0; mt < 2; mt++) {
            int s = s0 + mt * 16;
            #pragma unroll
            for (int nt = 0; nt < 2; nt++) {
                int n = nt * 8 + nb;
                #pragma unroll
                for (int r = 0; r < 4; r++) {
                    int nn = n + (r & 1);
                    int ss = s + (r >> 1) * 8;
                    float v = d[mt][nt][r];
                    if (nn == 15)
                        sm[O_DENS + ss] = expf(fminf(fmaxf(v, -15.0f), 15.0f));
                    else
                        sm[O_ACTA + (16 + nn) * 136 + ss] = v;
                }
            }
        }
        __syncthreads();
    }

    // ============ SC1: ci[32] @ Wc1 -> relu -> ACT_B ============
    {
        float d[2][8][4];
        gemm3x<4, 8>(sm + O_ACTA, sm + O_C1B, sm + O_C1S, 72, lane, warp, d);
        __syncthreads();
        store_relu<8>(sm + O_ACTB, lane, warp, d);
        __syncthreads();
    }

    // ============ SC2: h @ Wc2 -> relu -> ACT_A ============
    {
        float d[2][8][4];
        gemm3x<8, 8>(sm + O_ACTB, sm + O_C2B, sm + O_C2S, 72, lane, warp, d);
        __syncthreads();
        store_relu<8>(sm + O_ACTA, lane, warp, d);
        __syncthreads();
    }

    // ============ SC3: h[64] @ Wc3[64][3] -> sigmoid rgb + density ============
    {
        float a0 = 0.f, a1 = 0.f, a2 = 0.f;
        #pragma unroll 8
        for (int k = 0; k < 64; k++) {
            float h = sm[O_ACTA + k * 136 + tid];
            a0 += h * sm[O_C3 + k * 3];
            a1 += h * sm[O_C3 + k * 3 + 1];
            a2 += h * sm[O_C3 + k * 3 + 2];
        }
        float4 o;
        o.x = 1.0f / (1.0f + expf(-a0));
        o.y = 1.0f / (1.0f + expf(-a1));
        o.z = 1.0f / (1.0f + expf(-a2));
        o.w = sm[O_DENS + tid];
        ((float4*)out)[base + tid] = o;
    }
}

// ---------------------------------------------------------------------------
// Launch
// ---------------------------------------------------------------------------
extern "C" void kernel_launch(void* const* d_in, const int* in_sizes, int n_in,
                              void* d_out, int out_size)
{
    const float* pts   = (const float*)d_in[0];
    const float* dirs  = (const float*)d_in[1];
    const float* ts    = (const float*)d_in[2];
    const float* yl[6], *yh[6];
    for (int i = 0; i < 6; i++) {
        yl[i] = (const float*)d_in[3 + 2*i];
        yh[i] = (const float*)d_in[4 + 2*i];
    }
    const float* Ws1 = (const float*)d_in[15];
    const float* Ws2 = (const float*)d_in[16];
    const float* Wc1 = (const float*)d_in[17];
    const float* Wc2 = (const float*)d_in[18];
    const float* Wc3 = (const float*)d_in[19];
    float* out = (float*)d_out;

    static bool attr_done = false;
    if (!attr_done) {
        cudaFuncSetAttribute(gather_kernel,
                             cudaFuncAttributeMaxDynamicSharedMemorySize,
                             GATHER_SMEM);
        cudaFuncSetAttribute(mlp_kernel,
                             cudaFuncAttributeMaxDynamicSharedMemorySize,
                             MLP_SMEM);
        attr_done = true;
    }

    expand_kernel<<<(N_COARSE + 7) / 8, 256>>>(
        yl[0], yh[0], yl[1], yh[1], yl[2], yh[2],
        yl[3], yh[3], yl[4], yh[4], yl[5], yh[5]);

    sh_kernel<<<R_RAYS / 256, 256>>>(dirs);

    gather_kernel<<<NSAMP / 128, 128, GATHER_SMEM>>>(pts, ts);

    mlp_kernel<<<NSAMP / 128, 128, MLP_SMEM>>>(Ws1, Ws2, Wc1, Wc2, Wc3, out);
}

// round 9
// speedup vs baseline: 2.4305x; 1.2040x over previous
#include <cuda_runtime.h>
#include <math.h>

// ---------------------------------------------------------------------------
// Problem constants
// ---------------------------------------------------------------------------
#define R_RAYS   8192
#define S_SAMP   64
#define NSAMP    (R_RAYS * S_SAMP)      // 524288
#define C_FEAT   32

__device__ __constant__ int d_J[6] = {0,0,0,1,1,2};
__device__ __constant__ int d_K[6] = {1,2,3,2,3,3};

__device__ __constant__ int d_cw[6]    = {64,64,50,64,50,50};
__device__ __constant__ int d_cbase[6] = {0,4096,8192,11392,15488,18688};
#define N_COARSE 21888

__device__ __constant__ int d_fw[6]    = {128,128,100,128,100,100};
__device__ __constant__ int d_fbase[6] = {0,16384,32768,45568,61952,74752};
#define N_FINE 87552

// ---------------------------------------------------------------------------
// Scratch (device globals; no runtime allocation allowed)
// ---------------------------------------------------------------------------
__device__ float g_hi[N_FINE * C_FEAT];
__device__ float g_lo[N_FINE * C_FEAT];
__device__ float g_feats[64 * NSAMP];         // feature-major [f][n]
__device__ float g_enc[R_RAYS * 16];

// ---------------------------------------------------------------------------
// tf32 helpers
// ---------------------------------------------------------------------------
__device__ __forceinline__ unsigned tf32_bits(float x) {
    unsigned u;
    asm("cvt.rna.tf32.f32 %0, %1;" : "=r"(u) : "f"(x));
    return u;
}
__device__ __forceinline__ float tf32_val(float x) {
    return __uint_as_float(tf32_bits(x));
}

__device__ __forceinline__ void mma_tf32(float* d,
    unsigned a0, unsigned a1, unsigned a2, unsigned a3,
    unsigned b0, unsigned b1)
{
    asm volatile(
        "mma.sync.aligned.m16n8k8.row.col.f32.tf32.tf32.f32 "
        "{%0,%1,%2,%3}, {%4,%5,%6,%7}, {%8,%9}, {%0,%1,%2,%3};"
        : "+f"(d[0]), "+f"(d[1]), "+f"(d[2]), "+f"(d[3])
        : "r"(a0), "r"(a1), "r"(a2), "r"(a3), "r"(b0), "r"(b1));
}

// ---------------------------------------------------------------------------
// Kernel 1: expand (yl, yh) -> hi / lo fine planes
// ---------------------------------------------------------------------------
__global__ void expand_kernel(
    const float* __restrict__ yl0, const float* __restrict__ yh0,
    const float* __restrict__ yl1, const float* __restrict__ yh1,
    const float* __restrict__ yl2, const float* __restrict__ yh2,
    const float* __restrict__ yl3, const float* __restrict__ yh3,
    const float* __restrict__ yl4, const float* __restrict__ yh4,
    const float* __restrict__ yl5, const float* __restrict__ yh5)
{
    const float* yls[6] = {yl0, yl1, yl2, yl3, yl4, yl5};
    const float* yhs[6] = {yh0, yh1, yh2, yh3, yh4, yh5};

    int warpIdx = (blockIdx.x * blockDim.x + threadIdx.x) >> 5;
    int lane    = threadIdx.x & 31;
    if (warpIdx >= N_COARSE) return;

    int p = 0;
    #pragma unroll
    for (int q = 1; q < 6; q++) if (warpIdx >= d_cbase[q]) p = q;

    int local = warpIdx - d_cbase[p];
    int w  = d_cw[p];
    int cy = local / w;
    int cx = local - cy * w;
    int hw = 64 * w;

    const float* yl = yls[p];
    const float* yh = yhs[p];

    float a  = yl[lane * hw + cy * w + cx];
    const float* yhc = yh + (size_t)lane * 3 * hw + cy * w + cx;
    float lh = yhc[0];
    float hl = yhc[hw];
    float hh = yhc[2 * hw];

    int W    = 2 * w;
    int base = d_fbase[p] + (2 * cy) * W + 2 * cx;
    int i00 = base * 32 + lane;
    int i01 = i00 + 32;
    int i10 = (base + W) * 32 + lane;
    int i11 = i10 + 32;

    g_hi[i00] = 0.5f * (a + lh + hl + hh);
    g_hi[i01] = 0.5f * (a + lh - hl - hh);
    g_hi[i10] = 0.5f * (a - lh + hl - hh);
    g_hi[i11] = 0.5f * (a - lh - hl + hh);

    float lv = 0.5f * a;
    g_lo[i00] = lv; g_lo[i01] = lv; g_lo[i10] = lv; g_lo[i11] = lv;
}

// ---------------------------------------------------------------------------
// Kernel 2: SH degree-4 encoding per ray
// ---------------------------------------------------------------------------
__global__ void sh_kernel(const float* __restrict__ dirs)
{
    int r = blockIdx.x * blockDim.x + threadIdx.x;
    if (r >= R_RAYS) return;
    float dx = dirs[3*r], dy = dirs[3*r+1], dz = dirs[3*r+2];
    float nrm = sqrtf(dx*dx + dy*dy + dz*dz);
    float x = dx / nrm, y = dy / nrm, z = dz / nrm;
    float xx = x*x, yy = y*y, zz = z*z;

    float* e = g_enc + r * 16;
    e[0]  = 0.28209479177387814f;
    e[1]  = -0.4886025119029199f * y;
    e[2]  =  0.4886025119029199f * z;
    e[3]  = -0.4886025119029199f * x;
    e[4]  =  1.0925484305920792f * x * y;
    e[5]  = -1.0925484305920792f * y * z;
    e[6]  =  0.31539156525252005f * (3.0f * zz - 1.0f);
    e[7]  = -1.0925484305920792f * x * z;
    e[8]  =  0.5462742152960396f * (xx - yy);
    e[9]  = -0.5900435899266435f * y * (3.0f * xx - yy);
    e[10] =  2.890611442640554f * x * y * z;
    e[11] = -0.4570457994644658f * y * (5.0f * zz - 1.0f);
    e[12] =  0.3731763325901154f * z * (5.0f * zz - 3.0f);
    e[13] = -0.4570457994644658f * x * (5.0f * zz - 1.0f);
    e[14] =  1.445305721320277f * z * (xx - yy);
    e[15] = -0.5900435899266435f * x * (xx - 3.0f * yy);
}

// ---------------------------------------------------------------------------
// Kernel 3: gather + bilerp + 6-way product -> g_feats (feature-major)
// ---------------------------------------------------------------------------
#define GW_AW    1152
#define GW_TILE  (64 * 33)
#define GW_WORDS (GW_AW + GW_TILE)
#define GATHER_SMEM (4 * GW_WORDS * 4)

__global__ void gather_kernel(const float* __restrict__ pts,
                              const float* __restrict__ tstamps)
{
    extern __shared__ float smem[];
    int warp = threadIdx.x >> 5;
    int lane = threadIdx.x & 31;

    float* aw   = smem + warp * GW_WORDS;
    float* tile = aw + GW_AW;

    int n0 = (blockIdx.x * 4 + warp) * 32;
    int n  = n0 + lane;

    float p4[4];
    p4[0] = pts[3*n + 0];
    p4[1] = pts[3*n + 1];
    p4[2] = pts[3*n + 2];
    p4[3] = tstamps[n >> 6] * 2.0f - 1.0f;

    #pragma unroll
    for (int m = 0; m < 6; m++) {
        float cy_ = p4[d_J[m]];
        float cx_ = p4[d_K[m]];
        int W = d_fw[m];

        float y = (cy_ + 1.0f) * 0.5f * 127.0f;
        float x = (cx_ + 1.0f) * 0.5f * (float)(W - 1);

        float fy = floorf(y);
        int y0 = (int)fminf(fmaxf(fy, 0.0f), 127.0f);
        float wy = fminf(fmaxf(y - (float)y0, 0.0f), 1.0f);
        int y1 = min(y0 + 1, 127);

        float fx = floorf(x);
        int x0 = (int)fminf(fmaxf(fx, 0.0f), (float)(W - 1));
        float wx = fminf(fmaxf(x - (float)x0, 0.0f), 1.0f);
        int x1 = min(x0 + 1, W - 1);

        int b = d_fbase[m];
        int a00 = (b + y0 * W + x0) * 32;
        int a01 = (b + y0 * W + x1) * 32;
        int a10 = (b + y1 * W + x0) * 32;
        int a11 = (b + y1 * W + x1) * 32;

        float* s = aw + lane * 36 + m * 6;
        ((int*)s)[0] = a00;
        ((int*)s)[1] = a01;
        ((int*)s)[2] = a10;
        ((int*)s)[3] = a11;
        s[4] = wy;
        s[5] = wx;
    }
    __syncwarp();

    for (int i = 0; i < 32; i++) {
        float ah = 1.0f, al = 1.0f;
        #pragma unroll
        for (int m = 0; m < 6; m++) {
            const float* s = aw + i * 36 + m * 6;
            int a00 = ((const int*)s)[0];
            int a01 = ((const int*)s)[1];
            int a10 = ((const int*)s)[2];
            int a11 = ((const int*)s)[3];
            float wy = s[4];
            float wx = s[5];
            float w00 = (1.0f - wy) * (1.0f - wx);
            float w01 = (1.0f - wy) * wx;
            float w10 = wy * (1.0f - wx);
            float w11 = wy * wx;

            float vh = w00 * __ldg(g_hi + a00 + lane)
                     + w01 * __ldg(g_hi + a01 + lane)
                     + w10 * __ldg(g_hi + a10 + lane)
                     + w11 * __ldg(g_hi + a11 + lane);
            float vl = w00 * __ldg(g_lo + a00 + lane)
                     + w01 * __ldg(g_lo + a01 + lane)
                     + w10 * __ldg(g_lo + a10 + lane)
                     + w11 * __ldg(g_lo + a11 + lane);
            ah *= vh;
            al *= vl;
        }
        tile[lane * 33 + i]        = ah;
        tile[(32 + lane) * 33 + i] = al;
    }
    __syncwarp();

    #pragma unroll 8
    for (int r = 0; r < 64; r++) {
        g_feats[r * NSAMP + n0 + lane] = tile[r * 33 + lane];
    }
}

// ---------------------------------------------------------------------------
// Kernel 4: tensor-core MLP (3xTF32 mma.sync).
// 256 threads / 8 warps per block; one 128-sample tile at a time, n-split:
//   warp w -> m-quarter (w & 3) of sample rows, n-half (w >> 2) of neurons.
// 8 tiles per block (grid 512) to amortize weight staging.
// smem layout identical to R7 (175616 B -> 1 block/SM, now 8 warps).
// ---------------------------------------------------------------------------
#define O_W1B   0
#define O_W1S   4608
#define O_W2B   9216
#define O_W2S   10752
#define O_C1B   12288
#define O_C1S   14592
#define O_C2B   16896
#define O_C2S   21504
#define O_C3    26112
#define O_ENC   26304
#define O_DENS  26336
#define O_ACTA  26496
#define O_ACTB  35200
#define MLP_SMEM (43904 * 4)
#define TILES_PER_BLOCK 8
#define MLP_THREADS 256

// GEMM: D[128 samples x n-range] = act(K x s) * W(K x n), 3xTF32.
// Warp computes NTW n-tiles starting at neuron nbase; m-rows [32*wm, 32*wm+32).
template<int NK, int NTW>
__device__ __forceinline__ void gemm3x(const float* __restrict__ act,
                                       const float* __restrict__ wb,
                                       const float* __restrict__ ws,
                                       int wstr, int nbase,
                                       int lane, int wm,
                                       float (&d)[2][NTW][4])
{
    #pragma unroll
    for (int mt = 0; mt < 2; mt++)
        #pragma unroll
        for (int nt = 0; nt < NTW; nt++)
            #pragma unroll
            for (int r = 0; r < 4; r++) d[mt][nt][r] = 0.0f;

    const int srow = wm * 32 + (lane >> 2);     // sample row (a-frag)
    const int kcol = lane & 3;                  // k within k-step
    const int ncol = lane >> 2;                 // n within n-tile (b-frag)

    #pragma unroll
    for (int kk = 0; kk < NK; kk++) {
        unsigned ab[2][4], as[2][4];
        #pragma unroll
        for (int mt = 0; mt < 2; mt++) {
            const float* ap = act + (kk * 8 + kcol) * 136 + srow + mt * 16;
            float r0 = ap[0];
            float r1 = ap[8];
            float r2 = ap[4 * 136];
            float r3 = ap[4 * 136 + 8];
            ab[mt][0] = tf32_bits(r0);
            ab[mt][1] = tf32_bits(r1);
            ab[mt][2] = tf32_bits(r2);
            ab[mt][3] = tf32_bits(r3);
            as[mt][0] = tf32_bits(r0 - __uint_as_float(ab[mt][0]));
            as[mt][1] = tf32_bits(r1 - __uint_as_float(ab[mt][1]));
            as[mt][2] = tf32_bits(r2 - __uint_as_float(ab[mt][2]));
            as[mt][3] = tf32_bits(r3 - __uint_as_float(ab[mt][3]));
        }
        const float* wpb = wb + (kk * 8 + kcol) * wstr + ncol + nbase;
        const float* wps = ws + (kk * 8 + kcol) * wstr + ncol + nbase;
        #pragma unroll
        for (int nt = 0; nt < NTW; nt++) {
            unsigned bb0 = __float_as_uint(wpb[nt * 8]);
            unsigned bb1 = __float_as_uint(wpb[4 * wstr + nt * 8]);
            unsigned bs0 = __float_as_uint(wps[nt * 8]);
            unsigned bs1 = __float_as_uint(wps[4 * wstr + nt * 8]);
            #pragma unroll
            for (int mt = 0; mt < 2; mt++) {
                mma_tf32(d[mt][nt], ab[mt][0], ab[mt][1], ab[mt][2], ab[mt][3], bb0, bb1);
                mma_tf32(d[mt][nt], as[mt][0], as[mt][1], as[mt][2], as[mt][3], bb0, bb1);
                mma_tf32(d[mt][nt], ab[mt][0], ab[mt][1], ab[mt][2], ab[mt][3], bs0, bs1);
            }
        }
    }
}

// store D with relu, transposed into act layout [n][136 + s]
template<int NTW>
__device__ __forceinline__ void store_relu(float* __restrict__ dst,
                                           int nbase, int lane, int wm,
                                           float (&d)[2][NTW][4])
{
    int s0 = wm * 32 + (lane >> 2);
    int nb = 2 * (lane & 3);
    #pragma unroll
    for (int mt = 0; mt < 2; mt++) {
        int s = s0 + mt * 16;
        #pragma unroll
        for (int nt = 0; nt < NTW; nt++) {
            int n = nbase + nt * 8 + nb;
            dst[n * 136 + s]           = fmaxf(d[mt][nt][0], 0.0f);
            dst[(n + 1) * 136 + s]     = fmaxf(d[mt][nt][1], 0.0f);
            dst[n * 136 + s + 8]       = fmaxf(d[mt][nt][2], 0.0f);
            dst[(n + 1) * 136 + s + 8] = fmaxf(d[mt][nt][3], 0.0f);
        }
    }
}

__global__ void __launch_bounds__(MLP_THREADS) mlp_kernel(
    const float* __restrict__ Ws1, const float* __restrict__ Ws2,
    const float* __restrict__ Wc1, const float* __restrict__ Wc2,
    const float* __restrict__ Wc3, float* __restrict__ out)
{
    extern __shared__ __align__(16) float sm[];
    const int tid  = threadIdx.x;
    const int lane = tid & 31;
    const int warp = tid >> 5;
    const int wm   = warp & 3;          // m-quarter
    const int wg   = warp >> 2;         // n-half

    // ---- stage weights once per block (tf32 big/small split) ----
    for (int i = tid; i < 4096; i += MLP_THREADS) {
        int k = i >> 6, n = i & 63;
        float w = Ws1[i];
        float b = tf32_val(w);
        sm[O_W1B + k * 72 + n] = b;
        sm[O_W1S + k * 72 + n] = tf32_val(w - b);
        float w2 = Wc2[i];
        float b2 = tf32_val(w2);
        sm[O_C2B + k * 72 + n] = b2;
        sm[O_C2S + k * 72 + n] = tf32_val(w2 - b2);
    }
    for (int i = tid; i < 1024; i += MLP_THREADS) {
        int k = i >> 4, n = i & 15;
        float w = Ws2[i];
        float b = tf32_val(w);
        sm[O_W2B + k * 24 + n] = b;
        sm[O_W2S + k * 24 + n] = tf32_val(w - b);
    }
    for (int i = tid; i < 1984; i += MLP_THREADS) {
        int k = i >> 6, n = i & 63;
        float w = Wc1[i];
        float b = tf32_val(w);
        sm[O_C1B + k * 72 + n] = b;
        sm[O_C1S + k * 72 + n] = tf32_val(w - b);
    }
    if (tid < 72) {                         // zero pad row 31 of C1
        sm[O_C1B + 31 * 72 + tid] = 0.0f;
        sm[O_C1S + 31 * 72 + tid] = 0.0f;
    }
    for (int i = tid; i < 192; i += MLP_THREADS) sm[O_C3 + i] = Wc3[i];

    for (int t = 0; t < TILES_PER_BLOCK; t++) {
        const int base = (blockIdx.x * TILES_PER_BLOCK + t) * 128;

        // ensure previous tile's SC3 reads of ACT_A are done
        __syncthreads();

        // ---- stage feats tile [64][128] + enc ----
        #pragma unroll 4
        for (int i = tid; i < 2048; i += MLP_THREADS) {
            int k  = i >> 5;
            int c4 = i & 31;
            *(float4*)(sm + O_ACTA + k * 136 + 4 * c4) =
                *(const float4*)(g_feats + (size_t)k * NSAMP + base + 4 * c4);
        }
        if (tid < 32) sm[O_ENC + tid] = g_enc[((base >> 6) + (tid >> 4)) * 16 + (tid & 15)];
        __syncthreads();

        // ===== L1: feats[64] @ Wsig1 -> relu -> ACT_B =====
        {
            float d[2][4][4];
            gemm3x<8, 4>(sm + O_ACTA, sm + O_W1B, sm + O_W1S, 72, wg * 32, lane, wm, d);
            __syncthreads();                // all reads of ACT_A done
            store_relu<4>(sm + O_ACTB, wg * 32, lane, wm, d);
            // fill SC1 input rows 0..15 (SH enc) and row 31 (zero) in ACT_A
            for (int i = tid; i < 2048; i += MLP_THREADS) {
                int j = i >> 7, s = i & 127;
                sm[O_ACTA + j * 136 + s] = sm[O_ENC + (s >> 6) * 16 + j];
            }
            if (tid < 128) sm[O_ACTA + 31 * 136 + tid] = 0.0f;
            __syncthreads();
        }

        // ===== L2: h @ Wsig2 -> geo rows 16..30 of ACT_A, density =====
        {
            float d[2][1][4];
            gemm3x<8, 1>(sm + O_ACTB, sm + O_W2B, sm + O_W2S, 24, wg * 8, lane, wm, d);
            int s0 = wm * 32 + (lane >> 2);
            int nb = 2 * (lane & 3);
            #pragma unroll
            for (int mt = 0; mt < 2; mt++) {
                int s = s0 + mt * 16;
                int n = wg * 8 + nb;
                #pragma unroll
                for (int r = 0; r < 4; r++) {
                    int nn = n + (r & 1);
                    int ss = s + (r >> 1) * 8;
                    float v = d[mt][0][r];
                    if (nn == 15)
                        sm[O_DENS + ss] = expf(fminf(fmaxf(v, -15.0f), 15.0f));
                    else
                        sm[O_ACTA + (16 + nn) * 136 + ss] = v;
                }
            }
            __syncthreads();
        }

        // ===== SC1: ci[32] @ Wc1 -> relu -> ACT_B =====
        {
            float d[2][4][4];
            gemm3x<4, 4>(sm + O_ACTA, sm + O_C1B, sm + O_C1S, 72, wg * 32, lane, wm, d);
            __syncthreads();
            store_relu<4>(sm + O_ACTB, wg * 32, lane, wm, d);
            __syncthreads();
        }

        // ===== SC2: h @ Wc2 -> relu -> ACT_A =====
        {
            float d[2][4][4];
            gemm3x<8, 4>(sm + O_ACTB, sm + O_C2B, sm + O_C2S, 72, wg * 32, lane, wm, d);
            __syncthreads();                // all reads of ACT_A (SC1 inputs) done
            store_relu<4>(sm + O_ACTA, wg * 32, lane, wm, d);
            __syncthreads();
        }

        // ===== SC3: h[64] @ Wc3[64][3] -> sigmoid rgb + density =====
        if (tid < 128) {
            float a0 = 0.f, a1 = 0.f, a2 = 0.f;
            #pragma unroll 8
            for (int k = 0; k < 64; k++) {
                float h = sm[O_ACTA + k * 136 + tid];
                a0 += h * sm[O_C3 + k * 3];
                a1 += h * sm[O_C3 + k * 3 + 1];
                a2 += h * sm[O_C3 + k * 3 + 2];
            }
            float4 o;
            o.x = 1.0f / (1.0f + expf(-a0));
            o.y = 1.0f / (1.0f + expf(-a1));
            o.z = 1.0f / (1.0f + expf(-a2));
            o.w = sm[O_DENS + tid];
            ((float4*)out)[base + tid] = o;
        }
    }
}

// ---------------------------------------------------------------------------
// Launch
// ---------------------------------------------------------------------------
extern "C" void kernel_launch(void* const* d_in, const int* in_sizes, int n_in,
                              void* d_out, int out_size)
{
    const float* pts   = (const float*)d_in[0];
    const float* dirs  = (const float*)d_in[1];
    const float* ts    = (const float*)d_in[2];
    const float* yl[6], *yh[6];
    for (int i = 0; i < 6; i++) {
        yl[i] = (const float*)d_in[3 + 2*i];
        yh[i] = (const float*)d_in[4 + 2*i];
    }
    const float* Ws1 = (const float*)d_in[15];
    const float* Ws2 = (const float*)d_in[16];
    const float* Wc1 = (const float*)d_in[17];
    const float* Wc2 = (const float*)d_in[18];
    const float* Wc3 = (const float*)d_in[19];
    float* out = (float*)d_out;

    static bool attr_done = false;
    if (!attr_done) {
        cudaFuncSetAttribute(gather_kernel,
                             cudaFuncAttributeMaxDynamicSharedMemorySize,
                             GATHER_SMEM);
        cudaFuncSetAttribute(mlp_kernel,
                             cudaFuncAttributeMaxDynamicSharedMemorySize,
                             MLP_SMEM);
        attr_done = true;
    }

    expand_kernel<<<(N_COARSE + 7) / 8, 256>>>(
        yl[0], yh[0], yl[1], yh[1], yl[2], yh[2],
        yl[3], yh[3], yl[4], yh[4], yl[5], yh[5]);

    sh_kernel<<<R_RAYS / 256, 256>>>(dirs);

    gather_kernel<<<NSAMP / 128, 128, GATHER_SMEM>>>(pts, ts);

    mlp_kernel<<<(NSAMP / 128) / TILES_PER_BLOCK, MLP_THREADS, MLP_SMEM>>>(
        Ws1, Ws2, Wc1, Wc2, Wc3, out);
}